// round 1
// baseline (speedup 1.0000x reference)
#include <cuda_runtime.h>
#include <cstdint>

#define NM 50000
#define NP 50000
#define NN 100000          // total nodes
#define E_EDGES 1000000
#define IN_DIM 128
#define HID 256
#define LAT 64

// ---------------- device scratch (static: no allocations allowed) ----------------
__device__ __align__(16) float g_AX[(size_t)NN * 256];   // cols 0..127: mean-agg, 128..255: padded features
__device__ __align__(16) float g_H [(size_t)NN * 256];   // hidden
__device__ __align__(16) float g_UV[(size_t)NN * 128];   // cols 0..63: u = h@W2l^T, 64..127: v = h@W2r^T
__device__ __align__(16) float g_Z [(size_t)NN * 64];    // latent
__device__ int   g_deg[NN];
__device__ int   g_rowptr[NN];
__device__ int   g_cursor[NN];
__device__ int   g_col[2 * E_EDGES];
__device__ int   g_bsum[128];
__device__ __align__(16) float g_B1[256 * 256];  // B1[k][n]
__device__ __align__(16) float g_B2[256 * 128];  // B2[k][n]
__device__ __align__(16) float g_B3[64 * 128];   // B3[k][n]

// ---------------- small helpers ----------------
__device__ __forceinline__ float4 f4z() { return make_float4(0.f, 0.f, 0.f, 0.f); }
__device__ __forceinline__ void f4acc(float4& a, const float4& b) {
    a.x += b.x; a.y += b.y; a.z += b.z; a.w += b.w;
}

__device__ __forceinline__ int warpScanInc(int v) {
    #pragma unroll
    for (int o = 1; o < 32; o <<= 1) {
        int t = __shfl_up_sync(0xffffffffu, v, o);
        if ((threadIdx.x & 31) >= o) v += t;
    }
    return v;
}

// ---------------- init / graph build ----------------
__global__ void zero_counters() {
    int i = blockIdx.x * blockDim.x + threadIdx.x;
    if (i < NN) { g_deg[i] = 0; g_cursor[i] = 0; }
}

__global__ void pack_weights(const float* __restrict__ W1l, const float* __restrict__ W1r,
                             const float* __restrict__ W2l, const float* __restrict__ W2r,
                             const float* __restrict__ Wd) {
    int i = blockIdx.x * blockDim.x + threadIdx.x;
    if (i < 256 * 256) {
        int k = i >> 8, n = i & 255;
        g_B1[i] = (k < 128) ? W1l[n * 128 + k] : W1r[n * 128 + (k - 128)];
    } else if (i < 256 * 256 + 256 * 128) {
        int j = i - 256 * 256;
        int k = j >> 7, n = j & 127;
        g_B2[j] = (n < 64) ? W2l[n * 256 + k] : W2r[(n - 64) * 256 + k];
    } else if (i < 256 * 256 + 256 * 128 + 64 * 128) {
        int j = i - 256 * 256 - 256 * 128;
        int k = j >> 7, n = j & 127;
        g_B3[j] = Wd[n * 64 + k];
    }
}

__global__ void build_ax(const float* __restrict__ xm, const float* __restrict__ xp) {
    int t = blockIdx.x * blockDim.x + threadIdx.x;
    if (t >= NN * 32) return;
    int row = t >> 5, c4 = t & 31;
    float4 v;
    if (row < NM) {
        int cf = c4 * 4;
        if (cf < 96) v = *(const float4*)(xm + (size_t)row * 96 + cf);
        else         v = f4z();
    } else {
        v = *(const float4*)(xp + (size_t)(row - NM) * 128 + c4 * 4);
    }
    ((float4*)g_AX)[(size_t)row * 64 + 32 + c4] = v;
}

__global__ void deg_count(const int* __restrict__ ei) {
    int t = blockIdx.x * blockDim.x + threadIdx.x;
    if (t >= 2 * E_EDGES) return;
    int dst = (t < E_EDGES) ? (NM + ei[E_EDGES + t]) : ei[t - E_EDGES];
    atomicAdd(&g_deg[dst], 1);
}

__global__ void scanA(int n) {
    int i = blockIdx.x * 1024 + threadIdx.x;
    int v = (i < n) ? g_deg[i] : 0;
    int inc = warpScanInc(v);
    __shared__ int ws[32];
    int warp = threadIdx.x >> 5, lane = threadIdx.x & 31;
    if (lane == 31) ws[warp] = inc;
    __syncthreads();
    if (warp == 0) {
        int t = ws[lane];
        t = warpScanInc(t);
        ws[lane] = t;
    }
    __syncthreads();
    int base = (warp > 0) ? ws[warp - 1] : 0;
    if (i < n) g_rowptr[i] = base + inc - v;
    if (threadIdx.x == 1023) g_bsum[blockIdx.x] = base + inc;
}

__global__ void scanB(int nb) {
    int tid = threadIdx.x;  // 128 threads
    int v = (tid < nb) ? g_bsum[tid] : 0;
    int inc = warpScanInc(v);
    __shared__ int ws[4];
    if ((tid & 31) == 31) ws[tid >> 5] = inc;
    __syncthreads();
    int w = tid >> 5, base = 0;
    for (int i = 0; i < w; i++) base += ws[i];
    __syncthreads();
    if (tid < nb) g_bsum[tid] = base + inc - v;
}

__global__ void scanC(int n) {
    int i = blockIdx.x * 1024 + threadIdx.x;
    if (i < n) g_rowptr[i] += g_bsum[blockIdx.x];
}

__global__ void fill_csr(const int* __restrict__ ei) {
    int t = blockIdx.x * blockDim.x + threadIdx.x;
    if (t >= 2 * E_EDGES) return;
    int dst, src;
    if (t < E_EDGES) { dst = NM + ei[E_EDGES + t]; src = ei[t]; }
    else             { dst = ei[t - E_EDGES];      src = NM + ei[t]; }
    int pos = g_rowptr[dst] + atomicAdd(&g_cursor[dst], 1);
    g_col[pos] = src;
}

// ---------------- aggregation ----------------
// Layer 1: one warp per node; gather 128-wide feature rows (AX right half) -> mean -> AX left half.
__global__ void agg1_kernel() {
    int w = (blockIdx.x * blockDim.x + threadIdx.x) >> 5;
    if (w >= NN) return;
    int lane = threadIdx.x & 31;
    int start = g_rowptr[w];
    int d = g_deg[w];
    const float4* AX4 = (const float4*)g_AX;
    float4 a0 = f4z(), a1 = f4z();
    int j = 0;
    for (; j + 2 <= d; j += 2) {
        int s0 = __ldg(&g_col[start + j]);
        int s1 = __ldg(&g_col[start + j + 1]);
        float4 v0 = __ldg(&AX4[(size_t)s0 * 64 + 32 + lane]);
        float4 v1 = __ldg(&AX4[(size_t)s1 * 64 + 32 + lane]);
        f4acc(a0, v0); f4acc(a1, v1);
    }
    if (j < d) {
        int s0 = __ldg(&g_col[start + j]);
        float4 v0 = __ldg(&AX4[(size_t)s0 * 64 + 32 + lane]);
        f4acc(a0, v0);
    }
    float inv = 1.0f / fmaxf((float)d, 1.0f);
    float4 r = make_float4((a0.x + a1.x) * inv, (a0.y + a1.y) * inv,
                           (a0.z + a1.z) * inv, (a0.w + a1.w) * inv);
    ((float4*)g_AX)[(size_t)w * 64 + lane] = r;
}

// Layer 2 fused: 16 lanes per node; z = mean(u over nbrs) + v + b2
__global__ void agg2_kernel(const float* __restrict__ b2) {
    int t = blockIdx.x * blockDim.x + threadIdx.x;
    int node = t >> 4;
    if (node >= NN) return;
    int l = t & 15;
    int start = g_rowptr[node];
    int d = g_deg[node];
    const float4* UV4 = (const float4*)g_UV;
    float4 a0 = f4z(), a1 = f4z();
    int j = 0;
    for (; j + 2 <= d; j += 2) {
        int s0 = __ldg(&g_col[start + j]);
        int s1 = __ldg(&g_col[start + j + 1]);
        float4 v0 = __ldg(&UV4[(size_t)s0 * 32 + l]);
        float4 v1 = __ldg(&UV4[(size_t)s1 * 32 + l]);
        f4acc(a0, v0); f4acc(a1, v1);
    }
    if (j < d) {
        int s0 = __ldg(&g_col[start + j]);
        float4 v0 = __ldg(&UV4[(size_t)s0 * 32 + l]);
        f4acc(a0, v0);
    }
    float inv = 1.0f / fmaxf((float)d, 1.0f);
    float4 vv = __ldg(&UV4[(size_t)node * 32 + 16 + l]);
    float4 bb = __ldg(&((const float4*)b2)[l]);
    float4 z;
    z.x = (a0.x + a1.x) * inv + vv.x + bb.x;
    z.y = (a0.y + a1.y) * inv + vv.y + bb.y;
    z.z = (a0.z + a1.z) * inv + vv.z + bb.z;
    z.w = (a0.w + a1.w) * inv + vv.w + bb.w;
    ((float4*)g_Z)[(size_t)node * 16 + l] = z;
}

// ---------------- GEMM: C[M,N] = A[M,K] * B[K,N] (B pre-packed K-major) ----------------
// EPI: 0 = none, 1 = bias + relu, 2 = bias
template <int EPI>
__global__ void __launch_bounds__(256) sgemm_kernel(
    const float* __restrict__ A, const float* __restrict__ B,
    const float* __restrict__ bias, float* __restrict__ C,
    int M, int N, int K)
{
    const int BM = 128, BN = 128, BK = 8;
    __shared__ float As[BK][BM];
    __shared__ float Bs[BK][BN];
    int tid = threadIdx.x;
    int tx = tid & 15, ty = tid >> 4;
    int m0 = blockIdx.x * BM;
    int n0 = blockIdx.y * BN;

    int ar = tid >> 1;            // 0..127 (A tile row)
    int ak = (tid & 1) * 4;       // 0 or 4 (A tile k)
    int bk = tid >> 5;            // 0..7   (B tile k)
    int bn = (tid & 31) * 4;      // B tile n

    float acc[8][8];
    #pragma unroll
    for (int i = 0; i < 8; i++)
        #pragma unroll
        for (int j = 0; j < 8; j++) acc[i][j] = 0.f;

    for (int k0 = 0; k0 < K; k0 += BK) {
        float4 av;
        int arow = m0 + ar;
        if (arow < M) av = *(const float4*)(A + (size_t)arow * K + k0 + ak);
        else          av = f4z();
        As[ak + 0][ar] = av.x; As[ak + 1][ar] = av.y;
        As[ak + 2][ar] = av.z; As[ak + 3][ar] = av.w;
        *(float4*)&Bs[bk][bn] = *(const float4*)(B + (size_t)(k0 + bk) * N + n0 + bn);
        __syncthreads();
        #pragma unroll
        for (int kk = 0; kk < BK; kk++) {
            float a[8], b[8];
            *(float4*)&a[0] = *(const float4*)&As[kk][ty * 8];
            *(float4*)&a[4] = *(const float4*)&As[kk][ty * 8 + 4];
            *(float4*)&b[0] = *(const float4*)&Bs[kk][tx * 8];
            *(float4*)&b[4] = *(const float4*)&Bs[kk][tx * 8 + 4];
            #pragma unroll
            for (int i = 0; i < 8; i++)
                #pragma unroll
                for (int j = 0; j < 8; j++)
                    acc[i][j] += a[i] * b[j];
        }
        __syncthreads();
    }

    #pragma unroll
    for (int i = 0; i < 8; i++) {
        int m = m0 + ty * 8 + i;
        if (m < M) {
            #pragma unroll
            for (int j = 0; j < 8; j += 4) {
                int n = n0 + tx * 8 + j;
                float4 r = make_float4(acc[i][j], acc[i][j + 1], acc[i][j + 2], acc[i][j + 3]);
                if (EPI >= 1) {
                    r.x += bias[n]; r.y += bias[n + 1]; r.z += bias[n + 2]; r.w += bias[n + 3];
                }
                if (EPI == 1) {
                    r.x = fmaxf(r.x, 0.f); r.y = fmaxf(r.y, 0.f);
                    r.z = fmaxf(r.z, 0.f); r.w = fmaxf(r.w, 0.f);
                }
                *(float4*)(C + (size_t)m * N + n) = r;
            }
        }
    }
}

// ---------------- edge logits ----------------
__global__ void logits_kernel(const int* __restrict__ ei, float* __restrict__ out) {
    int t = blockIdx.x * blockDim.x + threadIdx.x;
    int e = t >> 4;
    if (e >= E_EDGES) return;
    int l = t & 15;
    int p = __ldg(&ei[e]);
    int m = __ldg(&ei[E_EDGES + e]);
    const float4* Z4 = (const float4*)g_Z;
    float4 a = __ldg(&Z4[(size_t)(NM + p) * 16 + l]);
    float4 b = __ldg(&Z4[(size_t)m * 16 + l]);
    float s = a.x * b.x + a.y * b.y + a.z * b.z + a.w * b.w;
    s += __shfl_xor_sync(0xffffffffu, s, 8);
    s += __shfl_xor_sync(0xffffffffu, s, 4);
    s += __shfl_xor_sync(0xffffffffu, s, 2);
    s += __shfl_xor_sync(0xffffffffu, s, 1);
    if (l == 0) out[e] = s;
}

// ---------------- launch ----------------
extern "C" void kernel_launch(void* const* d_in, const int* in_sizes, int n_in,
                              void* d_out, int out_size) {
    const float* x_member   = (const float*)d_in[0];
    const float* x_provider = (const float*)d_in[1];
    const int*   edge_index = (const int*)d_in[2];
    const float* W1l = (const float*)d_in[3];
    const float* W1r = (const float*)d_in[4];
    const float* b1  = (const float*)d_in[5];
    const float* W2l = (const float*)d_in[6];
    const float* W2r = (const float*)d_in[7];
    const float* b2  = (const float*)d_in[8];
    const float* Wd  = (const float*)d_in[9];
    const float* bd  = (const float*)d_in[10];
    float* out = (float*)d_out;

    float* g_H_p;  cudaGetSymbolAddress((void**)&g_H_p,  g_H);
    float* g_AX_p; cudaGetSymbolAddress((void**)&g_AX_p, g_AX);
    float* g_UV_p; cudaGetSymbolAddress((void**)&g_UV_p, g_UV);
    float* g_Z_p;  cudaGetSymbolAddress((void**)&g_Z_p,  g_Z);
    float* g_B1_p; cudaGetSymbolAddress((void**)&g_B1_p, g_B1);
    float* g_B2_p; cudaGetSymbolAddress((void**)&g_B2_p, g_B2);
    float* g_B3_p; cudaGetSymbolAddress((void**)&g_B3_p, g_B3);

    const int NB = (NN + 1023) / 1024;  // 98

    zero_counters<<<(NN + 255) / 256, 256>>>();
    pack_weights<<<(256 * 256 + 256 * 128 + 64 * 128 + 255) / 256, 256>>>(W1l, W1r, W2l, W2r, Wd);
    build_ax<<<(NN * 32 + 255) / 256, 256>>>(x_member, x_provider);
    deg_count<<<(2 * E_EDGES + 255) / 256, 256>>>(edge_index);
    scanA<<<NB, 1024>>>(NN);
    scanB<<<1, 128>>>(NB);
    scanC<<<NB, 1024>>>(NN);
    fill_csr<<<(2 * E_EDGES + 255) / 256, 256>>>(edge_index);

    // layer 1
    agg1_kernel<<<(NN * 32 + 255) / 256, 256>>>();
    {
        dim3 grid((NN + 127) / 128, 256 / 128);
        sgemm_kernel<1><<<grid, 256>>>(g_AX_p, g_B1_p, b1, g_H_p, NN, 256, 256);
    }
    // layer 2 pre-projection: UV = H @ [W2l^T | W2r^T]
    {
        dim3 grid((NN + 127) / 128, 1);
        sgemm_kernel<0><<<grid, 256>>>(g_H_p, g_B2_p, nullptr, g_UV_p, NN, 128, 256);
    }
    // layer 2 aggregation + z
    agg2_kernel<<<(NN * 16 + 255) / 256, 256>>>(b2);
    // decoder straight into d_out (member rows then provider rows are contiguous)
    {
        dim3 grid((NN + 127) / 128, 1);
        sgemm_kernel<2><<<grid, 256>>>(g_Z_p, g_B3_p, bd, out, NN, 128, 64);
    }
    // edge logits
    logits_kernel<<<(E_EDGES * 16 + 255) / 256, 256>>>(edge_index, out + (size_t)2 * NM * 128);

    (void)in_sizes; (void)n_in; (void)out_size;
}

// round 3
// speedup vs baseline: 1.8137x; 1.8137x over previous
#include <cuda_runtime.h>
#include <cstdint>

#define NM 50000
#define NP 50000
#define NN 100000          // total nodes
#define E_EDGES 1000000

// ---------------- device scratch (static: no allocations allowed) ----------------
__device__ __align__(16) float g_AX[(size_t)NN * 256];   // cols 0..127: mean-agg, 128..255: padded features
__device__ __align__(16) float g_H [(size_t)NN * 256];   // hidden
__device__ __align__(16) float g_UV[(size_t)NN * 128];   // cols 0..63: u, 64..127: v
__device__ __align__(16) float g_Z [(size_t)NN * 64];    // latent
__device__ int   g_deg[NN];
__device__ int   g_rowptr[NN];
__device__ int   g_cursor[NN];
__device__ int   g_col[2 * E_EDGES];
__device__ int   g_bsum[128];
__device__ __align__(16) float g_B1[256 * 256];  // [n][k] n-major
__device__ __align__(16) float g_B2[128 * 256];  // [n][k] n-major

// ---------------- small helpers ----------------
__device__ __forceinline__ float4 f4z() { return make_float4(0.f, 0.f, 0.f, 0.f); }
__device__ __forceinline__ void f4acc(float4& a, const float4& b) {
    a.x += b.x; a.y += b.y; a.z += b.z; a.w += b.w;
}

__device__ __forceinline__ int warpScanInc(int v) {
    #pragma unroll
    for (int o = 1; o < 32; o <<= 1) {
        int t = __shfl_up_sync(0xffffffffu, v, o);
        if ((threadIdx.x & 31) >= o) v += t;
    }
    return v;
}

__device__ __forceinline__ uint32_t s2u(const void* p) {
    uint32_t a;
    asm("{ .reg .u64 t; cvta.to.shared.u64 t, %1; cvt.u32.u64 %0, t; }" : "=r"(a) : "l"(p));
    return a;
}
__device__ __forceinline__ uint32_t f2tf(float x) {
    uint32_t r; asm("cvt.rna.tf32.f32 %0, %1;" : "=r"(r) : "f"(x)); return r;
}
__device__ __forceinline__ void mma8(float* c, const uint32_t* a, uint32_t b0, uint32_t b1) {
    asm volatile(
        "mma.sync.aligned.m16n8k8.row.col.f32.tf32.tf32.f32 "
        "{%0,%1,%2,%3}, {%4,%5,%6,%7}, {%8,%9}, {%0,%1,%2,%3};"
        : "+f"(c[0]), "+f"(c[1]), "+f"(c[2]), "+f"(c[3])
        : "r"(a[0]), "r"(a[1]), "r"(a[2]), "r"(a[3]), "r"(b0), "r"(b1));
}

// ---------------- init / graph build ----------------
__global__ void zero_counters() {
    int i = blockIdx.x * blockDim.x + threadIdx.x;
    if (i < NN) { g_deg[i] = 0; g_cursor[i] = 0; }
}

// pack weights N-major: B[n][k]
__global__ void pack_weights(const float* __restrict__ W1l, const float* __restrict__ W1r,
                             const float* __restrict__ W2l, const float* __restrict__ W2r) {
    int i = blockIdx.x * blockDim.x + threadIdx.x;
    if (i < 256 * 256) {
        int n = i >> 8, k = i & 255;
        g_B1[n * 256 + k] = (k < 128) ? W1l[n * 128 + k] : W1r[n * 128 + (k - 128)];
    } else if (i < 256 * 256 + 128 * 256) {
        int j = i - 256 * 256;
        int n = j >> 8, k = j & 255;
        g_B2[n * 256 + k] = (n < 64) ? W2l[n * 256 + k] : W2r[(n - 64) * 256 + k];
    }
}

__global__ void build_ax(const float* __restrict__ xm, const float* __restrict__ xp) {
    int t = blockIdx.x * blockDim.x + threadIdx.x;
    if (t >= NN * 32) return;
    int row = t >> 5, c4 = t & 31;
    float4 v;
    if (row < NM) {
        int cf = c4 * 4;
        if (cf < 96) v = *(const float4*)(xm + (size_t)row * 96 + cf);
        else         v = f4z();
    } else {
        v = *(const float4*)(xp + (size_t)(row - NM) * 128 + c4 * 4);
    }
    ((float4*)g_AX)[(size_t)row * 64 + 32 + c4] = v;
}

__global__ void deg_count(const int* __restrict__ ei) {
    int t = blockIdx.x * blockDim.x + threadIdx.x;
    if (t >= 2 * E_EDGES) return;
    int dst = (t < E_EDGES) ? (NM + ei[E_EDGES + t]) : ei[t - E_EDGES];
    atomicAdd(&g_deg[dst], 1);
}

__global__ void scanA(int n) {
    int i = blockIdx.x * 1024 + threadIdx.x;
    int v = (i < n) ? g_deg[i] : 0;
    int inc = warpScanInc(v);
    __shared__ int ws[32];
    int warp = threadIdx.x >> 5, lane = threadIdx.x & 31;
    if (lane == 31) ws[warp] = inc;
    __syncthreads();
    if (warp == 0) {
        int t = ws[lane];
        t = warpScanInc(t);
        ws[lane] = t;
    }
    __syncthreads();
    int base = (warp > 0) ? ws[warp - 1] : 0;
    if (i < n) g_rowptr[i] = base + inc - v;
    if (threadIdx.x == 1023) g_bsum[blockIdx.x] = base + inc;
}

__global__ void scanB(int nb) {
    int tid = threadIdx.x;  // 128 threads
    int v = (tid < nb) ? g_bsum[tid] : 0;
    int inc = warpScanInc(v);
    __shared__ int ws[4];
    if ((tid & 31) == 31) ws[tid >> 5] = inc;
    __syncthreads();
    int w = tid >> 5, base = 0;
    for (int i = 0; i < w; i++) base += ws[i];
    __syncthreads();
    if (tid < nb) g_bsum[tid] = base + inc - v;
}

__global__ void scanC(int n) {
    int i = blockIdx.x * 1024 + threadIdx.x;
    if (i < n) g_rowptr[i] += g_bsum[blockIdx.x];
}

__global__ void fill_csr(const int* __restrict__ ei) {
    int t = blockIdx.x * blockDim.x + threadIdx.x;
    if (t >= 2 * E_EDGES) return;
    int dst, src;
    if (t < E_EDGES) { dst = NM + ei[E_EDGES + t]; src = ei[t]; }
    else             { dst = ei[t - E_EDGES];      src = NM + ei[t]; }
    int pos = g_rowptr[dst] + atomicAdd(&g_cursor[dst], 1);
    g_col[pos] = src;
}

// ---------------- aggregation ----------------
__global__ void agg1_kernel() {
    int w = (blockIdx.x * blockDim.x + threadIdx.x) >> 5;
    if (w >= NN) return;
    int lane = threadIdx.x & 31;
    int start = g_rowptr[w];
    int d = g_deg[w];
    const float4* AX4 = (const float4*)g_AX;
    float4 a0 = f4z(), a1 = f4z();
    int j = 0;
    for (; j + 2 <= d; j += 2) {
        int s0 = __ldg(&g_col[start + j]);
        int s1 = __ldg(&g_col[start + j + 1]);
        float4 v0 = __ldg(&AX4[(size_t)s0 * 64 + 32 + lane]);
        float4 v1 = __ldg(&AX4[(size_t)s1 * 64 + 32 + lane]);
        f4acc(a0, v0); f4acc(a1, v1);
    }
    if (j < d) {
        int s0 = __ldg(&g_col[start + j]);
        float4 v0 = __ldg(&AX4[(size_t)s0 * 64 + 32 + lane]);
        f4acc(a0, v0);
    }
    float inv = 1.0f / fmaxf((float)d, 1.0f);
    float4 r = make_float4((a0.x + a1.x) * inv, (a0.y + a1.y) * inv,
                           (a0.z + a1.z) * inv, (a0.w + a1.w) * inv);
    ((float4*)g_AX)[(size_t)w * 64 + lane] = r;
}

__global__ void agg2_kernel(const float* __restrict__ b2) {
    int t = blockIdx.x * blockDim.x + threadIdx.x;
    int node = t >> 4;
    if (node >= NN) return;
    int l = t & 15;
    int start = g_rowptr[node];
    int d = g_deg[node];
    const float4* UV4 = (const float4*)g_UV;
    float4 a0 = f4z(), a1 = f4z();
    int j = 0;
    for (; j + 2 <= d; j += 2) {
        int s0 = __ldg(&g_col[start + j]);
        int s1 = __ldg(&g_col[start + j + 1]);
        float4 v0 = __ldg(&UV4[(size_t)s0 * 32 + l]);
        float4 v1 = __ldg(&UV4[(size_t)s1 * 32 + l]);
        f4acc(a0, v0); f4acc(a1, v1);
    }
    if (j < d) {
        int s0 = __ldg(&g_col[start + j]);
        float4 v0 = __ldg(&UV4[(size_t)s0 * 32 + l]);
        f4acc(a0, v0);
    }
    float inv = 1.0f / fmaxf((float)d, 1.0f);
    float4 vv = __ldg(&UV4[(size_t)node * 32 + 16 + l]);
    float4 bb = __ldg(&((const float4*)b2)[l]);
    float4 z;
    z.x = (a0.x + a1.x) * inv + vv.x + bb.x;
    z.y = (a0.y + a1.y) * inv + vv.y + bb.y;
    z.z = (a0.z + a1.z) * inv + vv.z + bb.z;
    z.w = (a0.w + a1.w) * inv + vv.w + bb.w;
    ((float4*)g_Z)[(size_t)node * 16 + l] = z;
}

// ---------------- tf32 mma.sync GEMM: C[M,N] = A[M,K] @ Bw[N,K]^T ----------------
// Tile 128x128, BK=32, 256 threads = 8 warps (4 m x 2 n), warp tile 32x64.
// EPI: 0 = none, 1 = bias+relu, 2 = bias
#define SROW 36            // floats per smem row (32 data + 4 pad)
#define TILE_F (128 * SROW)

template <int EPI>
__global__ void __launch_bounds__(256, 2) tc_gemm(
    const float* __restrict__ A, const float* __restrict__ Bw,
    const float* __restrict__ bias, float* __restrict__ C,
    int M, int N, int K)
{
    extern __shared__ float smem[];
    // layout: [buf0: A|B][buf1: A|B]
    float* bufA[2] = { smem,              smem + 2 * TILE_F };
    float* bufB[2] = { smem + TILE_F,     smem + 3 * TILE_F };

    const int tid  = threadIdx.x;
    const int lane = tid & 31, warp = tid >> 5;
    const int warp_m = warp & 3, warp_n = warp >> 2;
    const int g = lane >> 2, tig = lane & 3;
    const int m0 = blockIdx.x * 128;
    const int n0 = blockIdx.y * 128;
    const int NC = K >> 5;

    float acc[2][8][4];
    #pragma unroll
    for (int mt = 0; mt < 2; mt++)
        #pragma unroll
        for (int nt = 0; nt < 8; nt++)
            #pragma unroll
            for (int j = 0; j < 4; j++) acc[mt][nt][j] = 0.f;

    // ---- staging (cp.async raw fp32) ----
    auto stage = [&](int c) {
        float* As = bufA[c & 1];
        float* Bs = bufB[c & 1];
        const int k0 = c * 32;
        #pragma unroll
        for (int i = 0; i < 4; i++) {
            int slot = tid + i * 256;
            int row = slot >> 3, c4 = slot & 7;
            // A
            float* dA = As + row * SROW + c4 * 4;
            int gr = m0 + row;
            if (gr < M) {
                const float* sA = A + (size_t)gr * K + k0 + c4 * 4;
                uint32_t da = s2u(dA);
                asm volatile("cp.async.cg.shared.global [%0], [%1], 16;" :: "r"(da), "l"(sA));
            } else {
                *(float4*)dA = f4z();
            }
            // B (N rows always full tiles)
            float* dB = Bs + row * SROW + c4 * 4;
            const float* sB = Bw + (size_t)(n0 + row) * K + k0 + c4 * 4;
            uint32_t db = s2u(dB);
            asm volatile("cp.async.cg.shared.global [%0], [%1], 16;" :: "r"(db), "l"(sB));
        }
        asm volatile("cp.async.commit_group;" ::: "memory");
    };

    stage(0);
    for (int c = 0; c < NC; c++) {
        if (c + 1 < NC) stage(c + 1);
        else asm volatile("cp.async.commit_group;" ::: "memory");
        asm volatile("cp.async.wait_group 1;" ::: "memory");
        __syncthreads();

        const float* As = bufA[c & 1];
        const float* Bs = bufB[c & 1];
        #pragma unroll
        for (int ks = 0; ks < 4; ks++) {
            const int kb = ks * 8 + tig;
            uint32_t afr[2][4];
            #pragma unroll
            for (int mt = 0; mt < 2; mt++) {
                int r = warp_m * 32 + mt * 16 + g;
                afr[mt][0] = f2tf(As[r * SROW + kb]);
                afr[mt][1] = f2tf(As[(r + 8) * SROW + kb]);
                afr[mt][2] = f2tf(As[r * SROW + kb + 4]);
                afr[mt][3] = f2tf(As[(r + 8) * SROW + kb + 4]);
            }
            #pragma unroll
            for (int nt = 0; nt < 8; nt++) {
                int n = warp_n * 64 + nt * 8 + g;
                uint32_t b0 = f2tf(Bs[n * SROW + kb]);
                uint32_t b1 = f2tf(Bs[n * SROW + kb + 4]);
                mma8(acc[0][nt], afr[0], b0, b1);
                mma8(acc[1][nt], afr[1], b0, b1);
            }
        }
        __syncthreads();
    }

    // ---- epilogue ----
    #pragma unroll
    for (int mt = 0; mt < 2; mt++) {
        int r0 = m0 + warp_m * 32 + mt * 16 + g;
        #pragma unroll
        for (int nt = 0; nt < 8; nt++) {
            int col = n0 + warp_n * 64 + nt * 8 + 2 * tig;
            float2 v0 = make_float2(acc[mt][nt][0], acc[mt][nt][1]);
            float2 v1 = make_float2(acc[mt][nt][2], acc[mt][nt][3]);
            if (EPI >= 1) {
                float2 bb = *(const float2*)(bias + col);
                v0.x += bb.x; v0.y += bb.y;
                v1.x += bb.x; v1.y += bb.y;
            }
            if (EPI == 1) {
                v0.x = fmaxf(v0.x, 0.f); v0.y = fmaxf(v0.y, 0.f);
                v1.x = fmaxf(v1.x, 0.f); v1.y = fmaxf(v1.y, 0.f);
            }
            if (r0 < M)     *(float2*)(C + (size_t)r0 * N + col)       = v0;
            if (r0 + 8 < M) *(float2*)(C + (size_t)(r0 + 8) * N + col) = v1;
        }
    }
}

// ---------------- edge logits ----------------
__global__ void logits_kernel(const int* __restrict__ ei, float* __restrict__ out) {
    int t = blockIdx.x * blockDim.x + threadIdx.x;
    int e = t >> 4;
    if (e >= E_EDGES) return;
    int l = t & 15;
    int p = __ldg(&ei[e]);
    int m = __ldg(&ei[E_EDGES + e]);
    const float4* Z4 = (const float4*)g_Z;
    float4 a = __ldg(&Z4[(size_t)(NM + p) * 16 + l]);
    float4 b = __ldg(&Z4[(size_t)m * 16 + l]);
    float s = a.x * b.x + a.y * b.y + a.z * b.z + a.w * b.w;
    s += __shfl_xor_sync(0xffffffffu, s, 8);
    s += __shfl_xor_sync(0xffffffffu, s, 4);
    s += __shfl_xor_sync(0xffffffffu, s, 2);
    s += __shfl_xor_sync(0xffffffffu, s, 1);
    if (l == 0) out[e] = s;
}

// ---------------- launch ----------------
extern "C" void kernel_launch(void* const* d_in, const int* in_sizes, int n_in,
                              void* d_out, int out_size) {
    const float* x_member   = (const float*)d_in[0];
    const float* x_provider = (const float*)d_in[1];
    const int*   edge_index = (const int*)d_in[2];
    const float* W1l = (const float*)d_in[3];
    const float* W1r = (const float*)d_in[4];
    const float* b1  = (const float*)d_in[5];
    const float* W2l = (const float*)d_in[6];
    const float* W2r = (const float*)d_in[7];
    const float* b2  = (const float*)d_in[8];
    const float* Wd  = (const float*)d_in[9];
    const float* bd  = (const float*)d_in[10];
    float* out = (float*)d_out;

    float* g_H_p;  cudaGetSymbolAddress((void**)&g_H_p,  g_H);
    float* g_AX_p; cudaGetSymbolAddress((void**)&g_AX_p, g_AX);
    float* g_UV_p; cudaGetSymbolAddress((void**)&g_UV_p, g_UV);
    float* g_Z_p;  cudaGetSymbolAddress((void**)&g_Z_p,  g_Z);
    float* g_B1_p; cudaGetSymbolAddress((void**)&g_B1_p, g_B1);
    float* g_B2_p; cudaGetSymbolAddress((void**)&g_B2_p, g_B2);

    const int SMEM = 4 * TILE_F * (int)sizeof(float);  // 73728
    cudaFuncSetAttribute((const void*)tc_gemm<1>,
                         cudaFuncAttributeMaxDynamicSharedMemorySize, SMEM);
    cudaFuncSetAttribute((const void*)tc_gemm<0>,
                         cudaFuncAttributeMaxDynamicSharedMemorySize, SMEM);
    cudaFuncSetAttribute((const void*)tc_gemm<2>,
                         cudaFuncAttributeMaxDynamicSharedMemorySize, SMEM);

    const int NB = (NN + 1023) / 1024;  // 98
    const int GT = (NN + 127) / 128;    // 782

    zero_counters<<<(NN + 255) / 256, 256>>>();
    pack_weights<<<(256 * 256 + 128 * 256 + 255) / 256, 256>>>(W1l, W1r, W2l, W2r);
    build_ax<<<(NN * 32 + 255) / 256, 256>>>(x_member, x_provider);
    deg_count<<<(2 * E_EDGES + 255) / 256, 256>>>(edge_index);
    scanA<<<NB, 1024>>>(NN);
    scanB<<<1, 128>>>(NB);
    scanC<<<NB, 1024>>>(NN);
    fill_csr<<<(2 * E_EDGES + 255) / 256, 256>>>(edge_index);

    // layer 1: AX = [agg | x], H = relu(AX @ B1^T + b1)
    agg1_kernel<<<(NN * 32 + 255) / 256, 256>>>();
    tc_gemm<1><<<dim3(GT, 2), 256, SMEM>>>(g_AX_p, g_B1_p, b1, g_H_p, NN, 256, 256);

    // layer 2 pre-projection: UV = H @ [W2l|W2r]^T
    tc_gemm<0><<<dim3(GT, 1), 256, SMEM>>>(g_H_p, g_B2_p, nullptr, g_UV_p, NN, 128, 256);

    // layer 2 aggregation + z
    agg2_kernel<<<(NN * 16 + 255) / 256, 256>>>(b2);

    // decoder straight into d_out (Wd already [n][k] row-major)
    tc_gemm<2><<<dim3(GT, 1), 256, SMEM>>>(g_Z_p, Wd, bd, out, NN, 128, 64);

    // edge logits
    logits_kernel<<<(E_EDGES * 16 + 255) / 256, 256>>>(edge_index, out + (size_t)2 * NM * 128);

    (void)in_sizes; (void)n_in; (void)out_size;
}

// round 5
// speedup vs baseline: 2.4765x; 1.3655x over previous
#include <cuda_runtime.h>
#include <cuda_fp16.h>
#include <cstdint>

#define NM 50000
#define NP 50000
#define NN 100000          // total nodes
#define E_EDGES 1000000

// ---------------- device scratch (static: no allocations allowed) ----------------
__device__ __align__(16) __half g_AXh[(size_t)NN * 256];  // cols 0..127 mean-agg, 128..255 padded features
__device__ __align__(16) __half g_Hh [(size_t)NN * 256];  // hidden (half)
__device__ __align__(16) float  g_UV[(size_t)NN * 128];   // cols 0..63: u, 64..127: v (fp32)
__device__ __align__(16) float  g_Z [(size_t)NN * 64];    // latent fp32 (for logits)
__device__ __align__(16) __half g_Zh[(size_t)NN * 64];    // latent half (for decoder GEMM)
__device__ int   g_deg[NN];
__device__ int   g_rowptr[NN];
__device__ int   g_cursor[NN];
__device__ int   g_col[2 * E_EDGES];
__device__ int   g_bsum[128];
__device__ __align__(16) __half g_B1h[256 * 256];  // [n][k]
__device__ __align__(16) __half g_B2h[128 * 256];  // [n][k]
__device__ __align__(16) __half g_B3h[128 * 64];   // [n][k] (= Wd layout)

// ---------------- small helpers ----------------
__device__ __forceinline__ float4 f4z() { return make_float4(0.f, 0.f, 0.f, 0.f); }

__device__ __forceinline__ uint32_t h2u(__half2 h) {
    union { __half2 h; uint32_t u; } c; c.h = h; return c.u;
}
__device__ __forceinline__ __half2 u2h(uint32_t u) {
    union { uint32_t u; __half2 h; } c; c.u = u; return c.h;
}

__device__ __forceinline__ int warpScanInc(int v) {
    #pragma unroll
    for (int o = 1; o < 32; o <<= 1) {
        int t = __shfl_up_sync(0xffffffffu, v, o);
        if ((threadIdx.x & 31) >= o) v += t;
    }
    return v;
}

__device__ __forceinline__ uint32_t s2u(const void* p) {
    uint32_t a;
    asm("{ .reg .u64 t; cvta.to.shared.u64 t, %1; cvt.u32.u64 %0, t; }" : "=r"(a) : "l"(p));
    return a;
}

__device__ __forceinline__ void mma16(float* c, const uint32_t* a, uint32_t b0, uint32_t b1) {
    asm volatile(
        "mma.sync.aligned.m16n8k16.row.col.f32.f16.f16.f32 "
        "{%0,%1,%2,%3}, {%4,%5,%6,%7}, {%8,%9}, {%0,%1,%2,%3};"
        : "+f"(c[0]), "+f"(c[1]), "+f"(c[2]), "+f"(c[3])
        : "r"(a[0]), "r"(a[1]), "r"(a[2]), "r"(a[3]), "r"(b0), "r"(b1));
}

__device__ __forceinline__ uint4 f8_to_h8(float4 a, float4 b) {
    uint4 r;
    r.x = h2u(__floats2half2_rn(a.x, a.y));
    r.y = h2u(__floats2half2_rn(a.z, a.w));
    r.z = h2u(__floats2half2_rn(b.x, b.y));
    r.w = h2u(__floats2half2_rn(b.z, b.w));
    return r;
}

// ---------------- init / graph build ----------------
__global__ void zero_counters() {
    int i = blockIdx.x * blockDim.x + threadIdx.x;
    if (i < NN) { g_deg[i] = 0; g_cursor[i] = 0; }
}

// pack weights N-major as half: B[n][k]
__global__ void pack_weights(const float* __restrict__ W1l, const float* __restrict__ W1r,
                             const float* __restrict__ W2l, const float* __restrict__ W2r,
                             const float* __restrict__ Wd) {
    int i = blockIdx.x * blockDim.x + threadIdx.x;
    if (i < 256 * 256) {
        int n = i >> 8, k = i & 255;
        g_B1h[i] = __float2half((k < 128) ? W1l[n * 128 + k] : W1r[n * 128 + (k - 128)]);
    } else if (i < 256 * 256 + 128 * 256) {
        int j = i - 256 * 256;
        int n = j >> 8, k = j & 255;
        g_B2h[j] = __float2half((n < 64) ? W2l[n * 256 + k] : W2r[(n - 64) * 256 + k]);
    } else if (i < 256 * 256 + 128 * 256 + 128 * 64) {
        int j = i - 256 * 256 - 128 * 256;
        g_B3h[j] = __float2half(Wd[j]);
    }
}

// write padded features (half) into right half of AXh. 16 lanes per row, 8 cols each.
__global__ void build_ax(const float* __restrict__ xm, const float* __restrict__ xp) {
    int t = blockIdx.x * blockDim.x + threadIdx.x;
    if (t >= NN * 16) return;
    int row = t >> 4, l = t & 15;
    int col = l * 8;
    float4 v0 = f4z(), v1 = f4z();
    if (row < NM) {
        if (col < 96) {
            v0 = *(const float4*)(xm + (size_t)row * 96 + col);
            v1 = *(const float4*)(xm + (size_t)row * 96 + col + 4);
        }
    } else {
        const float* xr = xp + (size_t)(row - NM) * 128 + col;
        v0 = *(const float4*)xr;
        v1 = *(const float4*)(xr + 4);
    }
    ((uint4*)g_AXh)[(size_t)row * 32 + 16 + l] = f8_to_h8(v0, v1);
}

__global__ void deg_count(const int* __restrict__ ei) {
    int t = blockIdx.x * blockDim.x + threadIdx.x;
    if (t >= 2 * E_EDGES) return;
    int dst = (t < E_EDGES) ? (NM + ei[E_EDGES + t]) : ei[t - E_EDGES];
    atomicAdd(&g_deg[dst], 1);
}

__global__ void scanA(int n) {
    int i = blockIdx.x * 1024 + threadIdx.x;
    int v = (i < n) ? g_deg[i] : 0;
    int inc = warpScanInc(v);
    __shared__ int ws[32];
    int warp = threadIdx.x >> 5, lane = threadIdx.x & 31;
    if (lane == 31) ws[warp] = inc;
    __syncthreads();
    if (warp == 0) {
        int t = ws[lane];
        t = warpScanInc(t);
        ws[lane] = t;
    }
    __syncthreads();
    int base = (warp > 0) ? ws[warp - 1] : 0;
    if (i < n) g_rowptr[i] = base + inc - v;
    if (threadIdx.x == 1023) g_bsum[blockIdx.x] = base + inc;
}

__global__ void scanB(int nb) {
    int tid = threadIdx.x;  // 128 threads
    int v = (tid < nb) ? g_bsum[tid] : 0;
    int inc = warpScanInc(v);
    __shared__ int ws[4];
    if ((tid & 31) == 31) ws[tid >> 5] = inc;
    __syncthreads();
    int w = tid >> 5, base = 0;
    for (int i = 0; i < w; i++) base += ws[i];
    __syncthreads();
    if (tid < nb) g_bsum[tid] = base + inc - v;
}

__global__ void scanC(int n) {
    int i = blockIdx.x * 1024 + threadIdx.x;
    if (i < n) g_rowptr[i] += g_bsum[blockIdx.x];
}

__global__ void fill_csr(const int* __restrict__ ei) {
    int t = blockIdx.x * blockDim.x + threadIdx.x;
    if (t >= 2 * E_EDGES) return;
    int dst, src;
    if (t < E_EDGES) { dst = NM + ei[E_EDGES + t]; src = ei[t]; }
    else             { dst = ei[t - E_EDGES];      src = NM + ei[t]; }
    int pos = g_rowptr[dst] + atomicAdd(&g_cursor[dst], 1);
    g_col[pos] = src;
}

// ---------------- aggregation ----------------
// Layer 1: 16 lanes per node; gather half feature rows (256B each), mean in fp32, write half.
__global__ void agg1_kernel() {
    int t = blockIdx.x * blockDim.x + threadIdx.x;
    int node = t >> 4;
    if (node >= NN) return;
    int l = t & 15;
    int start = g_rowptr[node];
    int d = g_deg[node];
    const uint4* AX4 = (const uint4*)g_AXh;
    float acc[8];
    #pragma unroll
    for (int i = 0; i < 8; i++) acc[i] = 0.f;
    int j = 0;
    for (; j + 2 <= d; j += 2) {
        int s0 = __ldg(&g_col[start + j]);
        int s1 = __ldg(&g_col[start + j + 1]);
        uint4 v0 = __ldg(&AX4[(size_t)s0 * 32 + 16 + l]);
        uint4 v1 = __ldg(&AX4[(size_t)s1 * 32 + 16 + l]);
        const uint32_t* p0 = &v0.x;
        const uint32_t* p1 = &v1.x;
        #pragma unroll
        for (int i = 0; i < 4; i++) {
            float2 f0 = __half22float2(u2h(p0[i]));
            float2 f1 = __half22float2(u2h(p1[i]));
            acc[2 * i]     += f0.x + f1.x;
            acc[2 * i + 1] += f0.y + f1.y;
        }
    }
    if (j < d) {
        int s0 = __ldg(&g_col[start + j]);
        uint4 v0 = __ldg(&AX4[(size_t)s0 * 32 + 16 + l]);
        const uint32_t* p0 = &v0.x;
        #pragma unroll
        for (int i = 0; i < 4; i++) {
            float2 f0 = __half22float2(u2h(p0[i]));
            acc[2 * i]     += f0.x;
            acc[2 * i + 1] += f0.y;
        }
    }
    float inv = 1.0f / fmaxf((float)d, 1.0f);
    uint4 o;
    o.x = h2u(__floats2half2_rn(acc[0] * inv, acc[1] * inv));
    o.y = h2u(__floats2half2_rn(acc[2] * inv, acc[3] * inv));
    o.z = h2u(__floats2half2_rn(acc[4] * inv, acc[5] * inv));
    o.w = h2u(__floats2half2_rn(acc[6] * inv, acc[7] * inv));
    ((uint4*)g_AXh)[(size_t)node * 32 + l] = o;
}

// Layer 2 fused: 16 lanes per node; z = mean(u over nbrs) + v + b2 (UV fp32), write fp32 + half
__global__ void agg2_kernel(const float* __restrict__ b2) {
    int t = blockIdx.x * blockDim.x + threadIdx.x;
    int node = t >> 4;
    if (node >= NN) return;
    int l = t & 15;
    int start = g_rowptr[node];
    int d = g_deg[node];
    const float4* UV4 = (const float4*)g_UV;
    float4 a0 = f4z(), a1 = f4z();
    int j = 0;
    for (; j + 2 <= d; j += 2) {
        int s0 = __ldg(&g_col[start + j]);
        int s1 = __ldg(&g_col[start + j + 1]);
        float4 v0 = __ldg(&UV4[(size_t)s0 * 32 + l]);
        float4 v1 = __ldg(&UV4[(size_t)s1 * 32 + l]);
        a0.x += v0.x; a0.y += v0.y; a0.z += v0.z; a0.w += v0.w;
        a1.x += v1.x; a1.y += v1.y; a1.z += v1.z; a1.w += v1.w;
    }
    if (j < d) {
        int s0 = __ldg(&g_col[start + j]);
        float4 v0 = __ldg(&UV4[(size_t)s0 * 32 + l]);
        a0.x += v0.x; a0.y += v0.y; a0.z += v0.z; a0.w += v0.w;
    }
    float inv = 1.0f / fmaxf((float)d, 1.0f);
    float4 vv = __ldg(&UV4[(size_t)node * 32 + 16 + l]);
    float4 bb = __ldg(&((const float4*)b2)[l]);
    float4 z;
    z.x = (a0.x + a1.x) * inv + vv.x + bb.x;
    z.y = (a0.y + a1.y) * inv + vv.y + bb.y;
    z.z = (a0.z + a1.z) * inv + vv.z + bb.z;
    z.w = (a0.w + a1.w) * inv + vv.w + bb.w;
    ((float4*)g_Z)[(size_t)node * 16 + l] = z;
    uint2 zh;
    zh.x = h2u(__floats2half2_rn(z.x, z.y));
    zh.y = h2u(__floats2half2_rn(z.z, z.w));
    ((uint2*)g_Zh)[(size_t)node * 16 + l] = zh;
}

// ---------------- fp16 mma.sync GEMM: C[M,N] = A[M,K] @ Bw[N,K]^T ----------------
// Tile 128x128, BK=32, 256 threads = 8 warps (4 m x 2 n), warp tile 32x64.
// EPI: 0 = none, 1 = bias+relu, 2 = bias.  OutT: __half or float.
#define SROWH 40                 // halves per smem row (32 data + 8 pad)
#define TILEH (128 * SROWH)      // halves per tile buffer (5120 -> 10240 B)

template <int EPI, typename OutT>
__global__ void __launch_bounds__(256, 2) hgemm(
    const __half* __restrict__ A, const __half* __restrict__ Bw,
    const float* __restrict__ bias, OutT* __restrict__ C,
    int M, int N, int K)
{
    extern __shared__ __half smh[];
    __half* bufA[2] = { smh,             smh + 2 * TILEH };
    __half* bufB[2] = { smh + TILEH,     smh + 3 * TILEH };

    const int tid  = threadIdx.x;
    const int lane = tid & 31, warp = tid >> 5;
    const int warp_m = warp & 3, warp_n = warp >> 2;
    const int g = lane >> 2, tig = lane & 3;
    const int m0 = blockIdx.x * 128;
    const int n0 = blockIdx.y * 128;
    const int NC = K >> 5;

    float acc[2][8][4];
    #pragma unroll
    for (int mt = 0; mt < 2; mt++)
        #pragma unroll
        for (int nt = 0; nt < 8; nt++)
            #pragma unroll
            for (int j = 0; j < 4; j++) acc[mt][nt][j] = 0.f;

    auto stage = [&](int c) {
        __half* As = bufA[c & 1];
        __half* Bs = bufB[c & 1];
        const int k0 = c * 32;
        #pragma unroll
        for (int i = 0; i < 2; i++) {
            int slot = tid + i * 256;            // 512 slots = 128 rows x 4 segs
            int row = slot >> 2, seg = slot & 3; // seg = 8 halves (16B)
            __half* dA = As + row * SROWH + seg * 8;
            int gr = m0 + row;
            if (gr < M) {
                const __half* sA = A + (size_t)gr * K + k0 + seg * 8;
                uint32_t da = s2u(dA);
                asm volatile("cp.async.cg.shared.global [%0], [%1], 16;" :: "r"(da), "l"(sA));
            } else {
                *(uint4*)dA = make_uint4(0, 0, 0, 0);
            }
            __half* dB = Bs + row * SROWH + seg * 8;
            const __half* sB = Bw + (size_t)(n0 + row) * K + k0 + seg * 8;
            uint32_t db = s2u(dB);
            asm volatile("cp.async.cg.shared.global [%0], [%1], 16;" :: "r"(db), "l"(sB));
        }
        asm volatile("cp.async.commit_group;" ::: "memory");
    };

    stage(0);
    for (int c = 0; c < NC; c++) {
        if (c + 1 < NC) stage(c + 1);
        else asm volatile("cp.async.commit_group;" ::: "memory");
        asm volatile("cp.async.wait_group 1;" ::: "memory");
        __syncthreads();

        const __half* As = bufA[c & 1];
        const __half* Bs = bufB[c & 1];
        #pragma unroll
        for (int ks = 0; ks < 2; ks++) {
            const int kb = ks * 16 + 2 * tig;
            uint32_t afr[2][4];
            #pragma unroll
            for (int mt = 0; mt < 2; mt++) {
                const __half* base = As + (warp_m * 32 + mt * 16 + g) * SROWH + kb;
                afr[mt][0] = *(const uint32_t*)(base);
                afr[mt][1] = *(const uint32_t*)(base + 8 * SROWH);
                afr[mt][2] = *(const uint32_t*)(base + 8);
                afr[mt][3] = *(const uint32_t*)(base + 8 * SROWH + 8);
            }
            #pragma unroll
            for (int nt = 0; nt < 8; nt++) {
                const __half* bb = Bs + (warp_n * 64 + nt * 8 + g) * SROWH + kb;
                uint32_t b0 = *(const uint32_t*)(bb);
                uint32_t b1 = *(const uint32_t*)(bb + 8);
                mma16(acc[0][nt], afr[0], b0, b1);
                mma16(acc[1][nt], afr[1], b0, b1);
            }
        }
        __syncthreads();
    }

    // ---- epilogue ----
    #pragma unroll
    for (int mt = 0; mt < 2; mt++) {
        int r0 = m0 + warp_m * 32 + mt * 16 + g;
        #pragma unroll
        for (int nt = 0; nt < 8; nt++) {
            int col = n0 + warp_n * 64 + nt * 8 + 2 * tig;
            float2 v0 = make_float2(acc[mt][nt][0], acc[mt][nt][1]);
            float2 v1 = make_float2(acc[mt][nt][2], acc[mt][nt][3]);
            if (EPI >= 1) {
                float2 bb = *(const float2*)(bias + col);
                v0.x += bb.x; v0.y += bb.y;
                v1.x += bb.x; v1.y += bb.y;
            }
            if (EPI == 1) {
                v0.x = fmaxf(v0.x, 0.f); v0.y = fmaxf(v0.y, 0.f);
                v1.x = fmaxf(v1.x, 0.f); v1.y = fmaxf(v1.y, 0.f);
            }
            if (sizeof(OutT) == 2) {
                uint32_t* Ch = (uint32_t*)C;
                if (r0 < M)     Ch[((size_t)r0 * N + col) >> 1]       = h2u(__floats2half2_rn(v0.x, v0.y));
                if (r0 + 8 < M) Ch[((size_t)(r0 + 8) * N + col) >> 1] = h2u(__floats2half2_rn(v1.x, v1.y));
            } else {
                float* Cf = (float*)C;
                if (r0 < M)     *(float2*)(Cf + (size_t)r0 * N + col)       = v0;
                if (r0 + 8 < M) *(float2*)(Cf + (size_t)(r0 + 8) * N + col) = v1;
            }
        }
    }
}

// ---------------- edge logits (fp32 Z) ----------------
__global__ void logits_kernel(const int* __restrict__ ei, float* __restrict__ out) {
    int t = blockIdx.x * blockDim.x + threadIdx.x;
    int e = t >> 4;
    if (e >= E_EDGES) return;
    int l = t & 15;
    int p = __ldg(&ei[e]);
    int m = __ldg(&ei[E_EDGES + e]);
    const float4* Z4 = (const float4*)g_Z;
    float4 a = __ldg(&Z4[(size_t)(NM + p) * 16 + l]);
    float4 b = __ldg(&Z4[(size_t)m * 16 + l]);
    float s = a.x * b.x + a.y * b.y + a.z * b.z + a.w * b.w;
    s += __shfl_xor_sync(0xffffffffu, s, 8);
    s += __shfl_xor_sync(0xffffffffu, s, 4);
    s += __shfl_xor_sync(0xffffffffu, s, 2);
    s += __shfl_xor_sync(0xffffffffu, s, 1);
    if (l == 0) out[e] = s;
}

// ---------------- launch ----------------
extern "C" void kernel_launch(void* const* d_in, const int* in_sizes, int n_in,
                              void* d_out, int out_size) {
    const float* x_member   = (const float*)d_in[0];
    const float* x_provider = (const float*)d_in[1];
    const int*   edge_index = (const int*)d_in[2];
    const float* W1l = (const float*)d_in[3];
    const float* W1r = (const float*)d_in[4];
    const float* b1  = (const float*)d_in[5];
    const float* W2l = (const float*)d_in[6];
    const float* W2r = (const float*)d_in[7];
    const float* b2  = (const float*)d_in[8];
    const float* Wd  = (const float*)d_in[9];
    const float* bd  = (const float*)d_in[10];
    float* out = (float*)d_out;

    __half* g_AXh_p; cudaGetSymbolAddress((void**)&g_AXh_p, g_AXh);
    __half* g_Hh_p;  cudaGetSymbolAddress((void**)&g_Hh_p,  g_Hh);
    float*  g_UV_p;  cudaGetSymbolAddress((void**)&g_UV_p,  g_UV);
    __half* g_Zh_p;  cudaGetSymbolAddress((void**)&g_Zh_p,  g_Zh);
    __half* g_B1_p;  cudaGetSymbolAddress((void**)&g_B1_p,  g_B1h);
    __half* g_B2_p;  cudaGetSymbolAddress((void**)&g_B2_p,  g_B2h);
    __half* g_B3_p;  cudaGetSymbolAddress((void**)&g_B3_p,  g_B3h);

    const int SMEM = 4 * TILEH * (int)sizeof(__half);  // 40960
    cudaFuncSetAttribute((const void*)hgemm<1, __half>,
                         cudaFuncAttributeMaxDynamicSharedMemorySize, SMEM);
    cudaFuncSetAttribute((const void*)hgemm<0, float>,
                         cudaFuncAttributeMaxDynamicSharedMemorySize, SMEM);
    cudaFuncSetAttribute((const void*)hgemm<2, float>,
                         cudaFuncAttributeMaxDynamicSharedMemorySize, SMEM);

    const int NB = (NN + 1023) / 1024;  // 98
    const int GT = (NN + 127) / 128;    // 782

    zero_counters<<<(NN + 255) / 256, 256>>>();
    pack_weights<<<(256 * 256 + 128 * 256 + 128 * 64 + 255) / 256, 256>>>(W1l, W1r, W2l, W2r, Wd);
    build_ax<<<(NN * 16 + 255) / 256, 256>>>(x_member, x_provider);
    deg_count<<<(2 * E_EDGES + 255) / 256, 256>>>(edge_index);
    scanA<<<NB, 1024>>>(NN);
    scanB<<<1, 128>>>(NB);
    scanC<<<NB, 1024>>>(NN);
    fill_csr<<<(2 * E_EDGES + 255) / 256, 256>>>(edge_index);

    // layer 1: AXh = [agg | x] (half), H = relu(AXh @ B1^T + b1) -> half
    agg1_kernel<<<(NN * 16 + 255) / 256, 256>>>();
    hgemm<1, __half><<<dim3(GT, 2), 256, SMEM>>>(g_AXh_p, g_B1_p, b1, g_Hh_p, NN, 256, 256);

    // layer 2 pre-projection: UV = H @ [W2l|W2r]^T  (fp32 out)
    hgemm<0, float><<<dim3(GT, 1), 256, SMEM>>>(g_Hh_p, g_B2_p, nullptr, g_UV_p, NN, 128, 256);

    // layer 2 aggregation + z (writes Z fp32 and Zh half)
    agg2_kernel<<<(NN * 16 + 255) / 256, 256>>>(b2);

    // decoder straight into d_out
    hgemm<2, float><<<dim3(GT, 1), 256, SMEM>>>(g_Zh_p, g_B3_p, bd, out, NN, 128, 64);

    // edge logits
    logits_kernel<<<(E_EDGES * 16 + 255) / 256, 256>>>(edge_index, out + (size_t)2 * NM * 128);

    (void)in_sizes; (void)n_in; (void)out_size;
}

// round 6
// speedup vs baseline: 2.5922x; 1.0467x over previous
#include <cuda_runtime.h>
#include <cuda_fp16.h>
#include <cstdint>

#define NM 50000
#define NP 50000
#define NN 100000          // total nodes
#define E_EDGES 1000000

// ---------------- device scratch (static: no allocations allowed) ----------------
__device__ __align__(16) __half g_AXh[(size_t)NN * 256];  // cols 0..127 mean-agg, 128..255 padded features
__device__ __align__(16) __half g_Hh [(size_t)NN * 256];  // hidden (half)
__device__ __align__(16) __half g_Uh [(size_t)NN * 64];   // u = h@W2l^T (half, gathered in agg2)
__device__ __align__(16) float  g_Vf [(size_t)NN * 64];   // v = h@W2r^T (fp32, read once per node)
__device__ __align__(16) __half g_Zh[(size_t)NN * 64];    // latent half (decoder GEMM + logits)
__device__ int   g_deg[NN];
__device__ int   g_rowptr[NN];
__device__ int   g_cursor[NN];
__device__ int   g_col[2 * E_EDGES];
__device__ int   g_bsum[128];
__device__ __align__(16) __half g_B1h[256 * 256];  // [n][k]
__device__ __align__(16) __half g_B2h[128 * 256];  // [n][k]
__device__ __align__(16) __half g_B3h[128 * 64];   // [n][k] (= Wd layout)

// ---------------- small helpers ----------------
__device__ __forceinline__ float4 f4z() { return make_float4(0.f, 0.f, 0.f, 0.f); }

__device__ __forceinline__ uint32_t h2u(__half2 h) {
    union { __half2 h; uint32_t u; } c; c.h = h; return c.u;
}
__device__ __forceinline__ __half2 u2h(uint32_t u) {
    union { uint32_t u; __half2 h; } c; c.u = u; return c.h;
}

__device__ __forceinline__ int warpScanInc(int v) {
    #pragma unroll
    for (int o = 1; o < 32; o <<= 1) {
        int t = __shfl_up_sync(0xffffffffu, v, o);
        if ((threadIdx.x & 31) >= o) v += t;
    }
    return v;
}

__device__ __forceinline__ uint32_t s2u(const void* p) {
    uint32_t a;
    asm("{ .reg .u64 t; cvta.to.shared.u64 t, %1; cvt.u32.u64 %0, t; }" : "=r"(a) : "l"(p));
    return a;
}

__device__ __forceinline__ void mma16(float* c, const uint32_t* a, uint32_t b0, uint32_t b1) {
    asm volatile(
        "mma.sync.aligned.m16n8k16.row.col.f32.f16.f16.f32 "
        "{%0,%1,%2,%3}, {%4,%5,%6,%7}, {%8,%9}, {%0,%1,%2,%3};"
        : "+f"(c[0]), "+f"(c[1]), "+f"(c[2]), "+f"(c[3])
        : "r"(a[0]), "r"(a[1]), "r"(a[2]), "r"(a[3]), "r"(b0), "r"(b1));
}

__device__ __forceinline__ uint4 f8_to_h8(float4 a, float4 b) {
    uint4 r;
    r.x = h2u(__floats2half2_rn(a.x, a.y));
    r.y = h2u(__floats2half2_rn(a.z, a.w));
    r.z = h2u(__floats2half2_rn(b.x, b.y));
    r.w = h2u(__floats2half2_rn(b.z, b.w));
    return r;
}

// ---------------- init / graph build ----------------
__global__ void zero_counters() {
    int i = blockIdx.x * blockDim.x + threadIdx.x;
    if (i < NN) g_deg[i] = 0;
}

// pack weights N-major as half: B[n][k]
__global__ void pack_weights(const float* __restrict__ W1l, const float* __restrict__ W1r,
                             const float* __restrict__ W2l, const float* __restrict__ W2r,
                             const float* __restrict__ Wd) {
    int i = blockIdx.x * blockDim.x + threadIdx.x;
    if (i < 256 * 256) {
        int n = i >> 8, k = i & 255;
        g_B1h[i] = __float2half((k < 128) ? W1l[n * 128 + k] : W1r[n * 128 + (k - 128)]);
    } else if (i < 256 * 256 + 128 * 256) {
        int j = i - 256 * 256;
        int n = j >> 8, k = j & 255;
        g_B2h[j] = __float2half((n < 64) ? W2l[n * 256 + k] : W2r[(n - 64) * 256 + k]);
    } else if (i < 256 * 256 + 128 * 256 + 128 * 64) {
        int j = i - 256 * 256 - 128 * 256;
        g_B3h[j] = __float2half(Wd[j]);
    }
}

// write padded features (half) into right half of AXh. 16 lanes per row, 8 cols each.
__global__ void build_ax(const float* __restrict__ xm, const float* __restrict__ xp) {
    int t = blockIdx.x * blockDim.x + threadIdx.x;
    if (t >= NN * 16) return;
    int row = t >> 4, l = t & 15;
    int col = l * 8;
    float4 v0 = f4z(), v1 = f4z();
    if (row < NM) {
        if (col < 96) {
            v0 = *(const float4*)(xm + (size_t)row * 96 + col);
            v1 = *(const float4*)(xm + (size_t)row * 96 + col + 4);
        }
    } else {
        const float* xr = xp + (size_t)(row - NM) * 128 + col;
        v0 = *(const float4*)xr;
        v1 = *(const float4*)(xr + 4);
    }
    ((uint4*)g_AXh)[(size_t)row * 32 + 16 + l] = f8_to_h8(v0, v1);
}

// one thread per edge: both directions
__global__ void deg_count(const int* __restrict__ ei) {
    int e = blockIdx.x * blockDim.x + threadIdx.x;
    if (e >= E_EDGES) return;
    int p = __ldg(&ei[e]);
    int m = __ldg(&ei[E_EDGES + e]);
    atomicAdd(&g_deg[NM + m], 1);
    atomicAdd(&g_deg[p], 1);
}

__global__ void scanA(int n) {
    int i = blockIdx.x * 1024 + threadIdx.x;
    int v = (i < n) ? g_deg[i] : 0;
    int inc = warpScanInc(v);
    __shared__ int ws[32];
    int warp = threadIdx.x >> 5, lane = threadIdx.x & 31;
    if (lane == 31) ws[warp] = inc;
    __syncthreads();
    if (warp == 0) {
        int t = ws[lane];
        t = warpScanInc(t);
        ws[lane] = t;
    }
    __syncthreads();
    int base = (warp > 0) ? ws[warp - 1] : 0;
    if (i < n) g_rowptr[i] = base + inc - v;
    if (threadIdx.x == 1023) g_bsum[blockIdx.x] = base + inc;
}

__global__ void scanB(int nb) {
    int tid = threadIdx.x;  // 128 threads
    int v = (tid < nb) ? g_bsum[tid] : 0;
    int inc = warpScanInc(v);
    __shared__ int ws[4];
    if ((tid & 31) == 31) ws[tid >> 5] = inc;
    __syncthreads();
    int w = tid >> 5, base = 0;
    for (int i = 0; i < w; i++) base += ws[i];
    __syncthreads();
    if (tid < nb) g_bsum[tid] = base + inc - v;
}

__global__ void scanC(int n) {
    int i = blockIdx.x * 1024 + threadIdx.x;
    if (i < n) {
        int rp = g_rowptr[i] + g_bsum[blockIdx.x];
        g_rowptr[i] = rp;
        g_cursor[i] = rp;     // cursor starts at row start: fill_csr atomics give absolute pos
    }
}

// one thread per edge: both directions, cursor holds absolute position
__global__ void fill_csr(const int* __restrict__ ei) {
    int e = blockIdx.x * blockDim.x + threadIdx.x;
    if (e >= E_EDGES) return;
    int p = __ldg(&ei[e]);
    int m = __ldg(&ei[E_EDGES + e]);
    int pos1 = atomicAdd(&g_cursor[NM + m], 1);
    g_col[pos1] = p;
    int pos2 = atomicAdd(&g_cursor[p], 1);
    g_col[pos2] = NM + m;
}

// ---------------- aggregation ----------------
// Layer 1: 16 lanes per node; gather half feature rows (256B each), mean in fp32, write half.
__global__ void agg1_kernel() {
    int t = blockIdx.x * blockDim.x + threadIdx.x;
    int node = t >> 4;
    if (node >= NN) return;
    int l = t & 15;
    int start = g_rowptr[node];
    int d = g_deg[node];
    const uint4* AX4 = (const uint4*)g_AXh;
    float acc[8];
    #pragma unroll
    for (int i = 0; i < 8; i++) acc[i] = 0.f;
    int j = 0;
    for (; j + 2 <= d; j += 2) {
        int s0 = __ldg(&g_col[start + j]);
        int s1 = __ldg(&g_col[start + j + 1]);
        uint4 v0 = __ldg(&AX4[(size_t)s0 * 32 + 16 + l]);
        uint4 v1 = __ldg(&AX4[(size_t)s1 * 32 + 16 + l]);
        const uint32_t* p0 = &v0.x;
        const uint32_t* p1 = &v1.x;
        #pragma unroll
        for (int i = 0; i < 4; i++) {
            float2 f0 = __half22float2(u2h(p0[i]));
            float2 f1 = __half22float2(u2h(p1[i]));
            acc[2 * i]     += f0.x + f1.x;
            acc[2 * i + 1] += f0.y + f1.y;
        }
    }
    if (j < d) {
        int s0 = __ldg(&g_col[start + j]);
        uint4 v0 = __ldg(&AX4[(size_t)s0 * 32 + 16 + l]);
        const uint32_t* p0 = &v0.x;
        #pragma unroll
        for (int i = 0; i < 4; i++) {
            float2 f0 = __half22float2(u2h(p0[i]));
            acc[2 * i]     += f0.x;
            acc[2 * i + 1] += f0.y;
        }
    }
    float inv = 1.0f / fmaxf((float)d, 1.0f);
    uint4 o;
    o.x = h2u(__floats2half2_rn(acc[0] * inv, acc[1] * inv));
    o.y = h2u(__floats2half2_rn(acc[2] * inv, acc[3] * inv));
    o.z = h2u(__floats2half2_rn(acc[4] * inv, acc[5] * inv));
    o.w = h2u(__floats2half2_rn(acc[6] * inv, acc[7] * inv));
    ((uint4*)g_AXh)[(size_t)node * 32 + l] = o;
}

// Layer 2 fused: 16 lanes per node; z = mean(u_half over nbrs) + v_f32 + b2, write Zh (half).
__global__ void agg2_kernel(const float* __restrict__ b2) {
    int t = blockIdx.x * blockDim.x + threadIdx.x;
    int node = t >> 4;
    if (node >= NN) return;
    int l = t & 15;
    int start = g_rowptr[node];
    int d = g_deg[node];
    const uint2* U2 = (const uint2*)g_Uh;   // 64 halves per row = 16 uint2
    float4 a0 = f4z(), a1 = f4z();
    int j = 0;
    for (; j + 2 <= d; j += 2) {
        int s0 = __ldg(&g_col[start + j]);
        int s1 = __ldg(&g_col[start + j + 1]);
        uint2 v0 = __ldg(&U2[(size_t)s0 * 16 + l]);
        uint2 v1 = __ldg(&U2[(size_t)s1 * 16 + l]);
        float2 f00 = __half22float2(u2h(v0.x)), f01 = __half22float2(u2h(v0.y));
        float2 f10 = __half22float2(u2h(v1.x)), f11 = __half22float2(u2h(v1.y));
        a0.x += f00.x; a0.y += f00.y; a0.z += f01.x; a0.w += f01.y;
        a1.x += f10.x; a1.y += f10.y; a1.z += f11.x; a1.w += f11.y;
    }
    if (j < d) {
        int s0 = __ldg(&g_col[start + j]);
        uint2 v0 = __ldg(&U2[(size_t)s0 * 16 + l]);
        float2 f00 = __half22float2(u2h(v0.x)), f01 = __half22float2(u2h(v0.y));
        a0.x += f00.x; a0.y += f00.y; a0.z += f01.x; a0.w += f01.y;
    }
    float inv = 1.0f / fmaxf((float)d, 1.0f);
    float4 vv = __ldg(&((const float4*)g_Vf)[(size_t)node * 16 + l]);
    float4 bb = __ldg(&((const float4*)b2)[l]);
    float4 z;
    z.x = (a0.x + a1.x) * inv + vv.x + bb.x;
    z.y = (a0.y + a1.y) * inv + vv.y + bb.y;
    z.z = (a0.z + a1.z) * inv + vv.z + bb.z;
    z.w = (a0.w + a1.w) * inv + vv.w + bb.w;
    uint2 zh;
    zh.x = h2u(__floats2half2_rn(z.x, z.y));
    zh.y = h2u(__floats2half2_rn(z.z, z.w));
    ((uint2*)g_Zh)[(size_t)node * 16 + l] = zh;
}

// ---------------- fp16 mma.sync GEMM: C[M,N] = A[M,K] @ Bw[N,K]^T ----------------
// Tile 128x128, BK=32, 256 threads = 8 warps (4 m x 2 n), warp tile 32x64.
// EPI: 0 = none, 1 = bias+relu, 2 = bias, 3 = UV split (cols 0-63 half->g_Uh, 64-127 f32->g_Vf)
#define SROWH 40                 // halves per smem row (32 data + 8 pad)
#define TILEH (128 * SROWH)      // halves per tile buffer

template <int EPI, typename OutT>
__global__ void __launch_bounds__(256, 2) hgemm(
    const __half* __restrict__ A, const __half* __restrict__ Bw,
    const float* __restrict__ bias, OutT* __restrict__ C,
    int M, int N, int K)
{
    extern __shared__ __half smh[];
    __half* bufA[2] = { smh,             smh + 2 * TILEH };
    __half* bufB[2] = { smh + TILEH,     smh + 3 * TILEH };

    const int tid  = threadIdx.x;
    const int lane = tid & 31, warp = tid >> 5;
    const int warp_m = warp & 3, warp_n = warp >> 2;
    const int g = lane >> 2, tig = lane & 3;
    const int m0 = blockIdx.x * 128;
    const int n0 = blockIdx.y * 128;
    const int NC = K >> 5;

    float acc[2][8][4];
    #pragma unroll
    for (int mt = 0; mt < 2; mt++)
        #pragma unroll
        for (int nt = 0; nt < 8; nt++)
            #pragma unroll
            for (int j = 0; j < 4; j++) acc[mt][nt][j] = 0.f;

    auto stage = [&](int c) {
        __half* As = bufA[c & 1];
        __half* Bs = bufB[c & 1];
        const int k0 = c * 32;
        #pragma unroll
        for (int i = 0; i < 2; i++) {
            int slot = tid + i * 256;            // 512 slots = 128 rows x 4 segs
            int row = slot >> 2, seg = slot & 3; // seg = 8 halves (16B)
            __half* dA = As + row * SROWH + seg * 8;
            int gr = m0 + row;
            if (gr < M) {
                const __half* sA = A + (size_t)gr * K + k0 + seg * 8;
                uint32_t da = s2u(dA);
                asm volatile("cp.async.cg.shared.global [%0], [%1], 16;" :: "r"(da), "l"(sA));
            } else {
                *(uint4*)dA = make_uint4(0, 0, 0, 0);
            }
            __half* dB = Bs + row * SROWH + seg * 8;
            const __half* sB = Bw + (size_t)(n0 + row) * K + k0 + seg * 8;
            uint32_t db = s2u(dB);
            asm volatile("cp.async.cg.shared.global [%0], [%1], 16;" :: "r"(db), "l"(sB));
        }
        asm volatile("cp.async.commit_group;" ::: "memory");
    };

    stage(0);
    for (int c = 0; c < NC; c++) {
        if (c + 1 < NC) stage(c + 1);
        else asm volatile("cp.async.commit_group;" ::: "memory");
        asm volatile("cp.async.wait_group 1;" ::: "memory");
        __syncthreads();

        const __half* As = bufA[c & 1];
        const __half* Bs = bufB[c & 1];
        #pragma unroll
        for (int ks = 0; ks < 2; ks++) {
            const int kb = ks * 16 + 2 * tig;
            uint32_t afr[2][4];
            #pragma unroll
            for (int mt = 0; mt < 2; mt++) {
                const __half* base = As + (warp_m * 32 + mt * 16 + g) * SROWH + kb;
                afr[mt][0] = *(const uint32_t*)(base);
                afr[mt][1] = *(const uint32_t*)(base + 8 * SROWH);
                afr[mt][2] = *(const uint32_t*)(base + 8);
                afr[mt][3] = *(const uint32_t*)(base + 8 * SROWH + 8);
            }
            #pragma unroll
            for (int nt = 0; nt < 8; nt++) {
                const __half* bb = Bs + (warp_n * 64 + nt * 8 + g) * SROWH + kb;
                uint32_t b0 = *(const uint32_t*)(bb);
                uint32_t b1 = *(const uint32_t*)(bb + 8);
                mma16(acc[0][nt], afr[0], b0, b1);
                mma16(acc[1][nt], afr[1], b0, b1);
            }
        }
        __syncthreads();
    }

    // ---- epilogue ----
    #pragma unroll
    for (int mt = 0; mt < 2; mt++) {
        int r0 = m0 + warp_m * 32 + mt * 16 + g;
        #pragma unroll
        for (int nt = 0; nt < 8; nt++) {
            int col = n0 + warp_n * 64 + nt * 8 + 2 * tig;
            float2 v0 = make_float2(acc[mt][nt][0], acc[mt][nt][1]);
            float2 v1 = make_float2(acc[mt][nt][2], acc[mt][nt][3]);
            if (EPI == 1 || EPI == 2) {
                float2 bb = *(const float2*)(bias + col);
                v0.x += bb.x; v0.y += bb.y;
                v1.x += bb.x; v1.y += bb.y;
            }
            if (EPI == 1) {
                v0.x = fmaxf(v0.x, 0.f); v0.y = fmaxf(v0.y, 0.f);
                v1.x = fmaxf(v1.x, 0.f); v1.y = fmaxf(v1.y, 0.f);
            }
            if (EPI == 3) {
                // split: cols 0-63 -> g_Uh (half), cols 64-127 -> g_Vf (fp32)
                if (col < 64) {
                    uint32_t* U = (uint32_t*)g_Uh;
                    if (r0 < M)     U[((size_t)r0 * 64 + col) >> 1]       = h2u(__floats2half2_rn(v0.x, v0.y));
                    if (r0 + 8 < M) U[((size_t)(r0 + 8) * 64 + col) >> 1] = h2u(__floats2half2_rn(v1.x, v1.y));
                } else {
                    int c2 = col - 64;
                    if (r0 < M)     *(float2*)(g_Vf + (size_t)r0 * 64 + c2)       = v0;
                    if (r0 + 8 < M) *(float2*)(g_Vf + (size_t)(r0 + 8) * 64 + c2) = v1;
                }
            } else if (sizeof(OutT) == 2) {
                uint32_t* Ch = (uint32_t*)C;
                if (r0 < M)     Ch[((size_t)r0 * N + col) >> 1]       = h2u(__floats2half2_rn(v0.x, v0.y));
                if (r0 + 8 < M) Ch[((size_t)(r0 + 8) * N + col) >> 1] = h2u(__floats2half2_rn(v1.x, v1.y));
            } else {
                float* Cf = (float*)C;
                if (r0 < M)     *(float2*)(Cf + (size_t)r0 * N + col)       = v0;
                if (r0 + 8 < M) *(float2*)(Cf + (size_t)(r0 + 8) * N + col) = v1;
            }
        }
    }
}

// ---------------- edge logits (half Z, fp32 accumulate) ----------------
__global__ void logits_kernel(const int* __restrict__ ei, float* __restrict__ out) {
    int t = blockIdx.x * blockDim.x + threadIdx.x;
    int e = t >> 4;
    if (e >= E_EDGES) return;
    int l = t & 15;
    int p = __ldg(&ei[e]);
    int m = __ldg(&ei[E_EDGES + e]);
    const uint2* Z2 = (const uint2*)g_Zh;
    uint2 a = __ldg(&Z2[(size_t)(NM + p) * 16 + l]);
    uint2 b = __ldg(&Z2[(size_t)m * 16 + l]);
    float2 a0 = __half22float2(u2h(a.x)), a1 = __half22float2(u2h(a.y));
    float2 b0 = __half22float2(u2h(b.x)), b1 = __half22float2(u2h(b.y));
    float s = a0.x * b0.x + a0.y * b0.y + a1.x * b1.x + a1.y * b1.y;
    s += __shfl_xor_sync(0xffffffffu, s, 8);
    s += __shfl_xor_sync(0xffffffffu, s, 4);
    s += __shfl_xor_sync(0xffffffffu, s, 2);
    s += __shfl_xor_sync(0xffffffffu, s, 1);
    if (l == 0) out[e] = s;
}

// ---------------- launch ----------------
extern "C" void kernel_launch(void* const* d_in, const int* in_sizes, int n_in,
                              void* d_out, int out_size) {
    const float* x_member   = (const float*)d_in[0];
    const float* x_provider = (const float*)d_in[1];
    const int*   edge_index = (const int*)d_in[2];
    const float* W1l = (const float*)d_in[3];
    const float* W1r = (const float*)d_in[4];
    const float* b1  = (const float*)d_in[5];
    const float* W2l = (const float*)d_in[6];
    const float* W2r = (const float*)d_in[7];
    const float* b2  = (const float*)d_in[8];
    const float* Wd  = (const float*)d_in[9];
    const float* bd  = (const float*)d_in[10];
    float* out = (float*)d_out;

    __half* g_AXh_p; cudaGetSymbolAddress((void**)&g_AXh_p, g_AXh);
    __half* g_Hh_p;  cudaGetSymbolAddress((void**)&g_Hh_p,  g_Hh);
    __half* g_Uh_p;  cudaGetSymbolAddress((void**)&g_Uh_p,  g_Uh);
    __half* g_Zh_p;  cudaGetSymbolAddress((void**)&g_Zh_p,  g_Zh);
    __half* g_B1_p;  cudaGetSymbolAddress((void**)&g_B1_p,  g_B1h);
    __half* g_B2_p;  cudaGetSymbolAddress((void**)&g_B2_p,  g_B2h);
    __half* g_B3_p;  cudaGetSymbolAddress((void**)&g_B3_p,  g_B3h);

    const int SMEM = 4 * TILEH * (int)sizeof(__half);  // 40960
    cudaFuncSetAttribute((const void*)hgemm<1, __half>,
                         cudaFuncAttributeMaxDynamicSharedMemorySize, SMEM);
    cudaFuncSetAttribute((const void*)hgemm<3, __half>,
                         cudaFuncAttributeMaxDynamicSharedMemorySize, SMEM);
    cudaFuncSetAttribute((const void*)hgemm<2, float>,
                         cudaFuncAttributeMaxDynamicSharedMemorySize, SMEM);

    const int NB = (NN + 1023) / 1024;  // 98
    const int GT = (NN + 127) / 128;    // 782

    zero_counters<<<(NN + 255) / 256, 256>>>();
    pack_weights<<<(256 * 256 + 128 * 256 + 128 * 64 + 255) / 256, 256>>>(W1l, W1r, W2l, W2r, Wd);
    build_ax<<<(NN * 16 + 255) / 256, 256>>>(x_member, x_provider);
    deg_count<<<(E_EDGES + 255) / 256, 256>>>(edge_index);
    scanA<<<NB, 1024>>>(NN);
    scanB<<<1, 128>>>(NB);
    scanC<<<NB, 1024>>>(NN);
    fill_csr<<<(E_EDGES + 255) / 256, 256>>>(edge_index);

    // layer 1: AXh = [agg | x] (half), H = relu(AXh @ B1^T + b1) -> half
    agg1_kernel<<<(NN * 16 + 255) / 256, 256>>>();
    hgemm<1, __half><<<dim3(GT, 2), 256, SMEM>>>(g_AXh_p, g_B1_p, b1, g_Hh_p, NN, 256, 256);

    // layer 2 pre-projection: [u|v] = H @ [W2l|W2r]^T, u->half g_Uh, v->fp32 g_Vf
    hgemm<3, __half><<<dim3(GT, 1), 256, SMEM>>>(g_Hh_p, g_B2_p, nullptr, g_Uh_p, NN, 128, 256);

    // layer 2 aggregation + z (writes Zh half)
    agg2_kernel<<<(NN * 16 + 255) / 256, 256>>>(b2);

    // decoder straight into d_out
    hgemm<2, float><<<dim3(GT, 1), 256, SMEM>>>(g_Zh_p, g_B3_p, bd, out, NN, 128, 64);

    // edge logits
    logits_kernel<<<(E_EDGES * 16 + 255) / 256, 256>>>(edge_index, out + (size_t)2 * NM * 128);

    (void)in_sizes; (void)n_in; (void)out_size;
}

// round 7
// speedup vs baseline: 3.0238x; 1.1665x over previous
#include <cuda_runtime.h>
#include <cuda_fp16.h>
#include <cstdint>

#define NM 50000
#define NP 50000
#define NN 100000          // total nodes
#define E_EDGES 1000000

// ---------------- device scratch (static: no allocations allowed) ----------------
__device__ __align__(16) __half g_AXh[(size_t)NN * 256];  // cols 0..127 mean-agg, 128..255 padded features
__device__ __align__(16) __half g_Hh [(size_t)NN * 256];  // hidden (half)
__device__ __align__(16) __half g_Uh [(size_t)NN * 64];   // u = h@W2l^T (half, gathered in agg2)
__device__ __align__(16) float  g_Vf [(size_t)NN * 64];   // v = h@W2r^T (fp32, read once per node)
__device__ __align__(16) __half g_Zh[(size_t)NN * 64];    // latent half (decoder GEMM + logits)
__device__ int   g_deg[NN];
__device__ int   g_rowptr[NN];
__device__ int   g_cursor[NN];
__device__ int   g_col[2 * E_EDGES];
__device__ int   g_bsum[128];
__device__ __align__(16) __half g_B1h[256 * 256];  // [n][k]
__device__ __align__(16) __half g_B2h[128 * 256];  // [n][k]
__device__ __align__(16) __half g_B3h[128 * 64];   // [n][k] (= Wd layout)

// ---------------- small helpers ----------------
__device__ __forceinline__ float4 f4z() { return make_float4(0.f, 0.f, 0.f, 0.f); }

__device__ __forceinline__ uint32_t h2u(__half2 h) {
    union { __half2 h; uint32_t u; } c; c.h = h; return c.u;
}
__device__ __forceinline__ __half2 u2h(uint32_t u) {
    union { uint32_t u; __half2 h; } c; c.u = u; return c.h;
}

__device__ __forceinline__ int warpScanInc(int v) {
    #pragma unroll
    for (int o = 1; o < 32; o <<= 1) {
        int t = __shfl_up_sync(0xffffffffu, v, o);
        if ((threadIdx.x & 31) >= o) v += t;
    }
    return v;
}

__device__ __forceinline__ uint32_t s2u(const void* p) {
    uint32_t a;
    asm("{ .reg .u64 t; cvta.to.shared.u64 t, %1; cvt.u32.u64 %0, t; }" : "=r"(a) : "l"(p));
    return a;
}

__device__ __forceinline__ void mma16(float* c, const uint32_t* a, uint32_t b0, uint32_t b1) {
    asm volatile(
        "mma.sync.aligned.m16n8k16.row.col.f32.f16.f16.f32 "
        "{%0,%1,%2,%3}, {%4,%5,%6,%7}, {%8,%9}, {%0,%1,%2,%3};"
        : "+f"(c[0]), "+f"(c[1]), "+f"(c[2]), "+f"(c[3])
        : "r"(a[0]), "r"(a[1]), "r"(a[2]), "r"(a[3]), "r"(b0), "r"(b1));
}

__device__ __forceinline__ uint4 f8_to_h8(float4 a, float4 b) {
    uint4 r;
    r.x = h2u(__floats2half2_rn(a.x, a.y));
    r.y = h2u(__floats2half2_rn(a.z, a.w));
    r.z = h2u(__floats2half2_rn(b.x, b.y));
    r.w = h2u(__floats2half2_rn(b.z, b.w));
    return r;
}

__device__ __forceinline__ void acc8(float* acc, uint4 v) {
    float2 f0 = __half22float2(u2h(v.x));
    float2 f1 = __half22float2(u2h(v.y));
    float2 f2 = __half22float2(u2h(v.z));
    float2 f3 = __half22float2(u2h(v.w));
    acc[0] += f0.x; acc[1] += f0.y;
    acc[2] += f1.x; acc[3] += f1.y;
    acc[4] += f2.x; acc[5] += f2.y;
    acc[6] += f3.x; acc[7] += f3.y;
}

// ---------------- init / graph build ----------------
__global__ void zero_counters() {
    int i = blockIdx.x * blockDim.x + threadIdx.x;
    if (i < NN) g_deg[i] = 0;
}

// pack weights N-major as half: B[n][k]
__global__ void pack_weights(const float* __restrict__ W1l, const float* __restrict__ W1r,
                             const float* __restrict__ W2l, const float* __restrict__ W2r,
                             const float* __restrict__ Wd) {
    int i = blockIdx.x * blockDim.x + threadIdx.x;
    if (i < 256 * 256) {
        int n = i >> 8, k = i & 255;
        g_B1h[i] = __float2half((k < 128) ? W1l[n * 128 + k] : W1r[n * 128 + (k - 128)]);
    } else if (i < 256 * 256 + 128 * 256) {
        int j = i - 256 * 256;
        int n = j >> 8, k = j & 255;
        g_B2h[j] = __float2half((n < 64) ? W2l[n * 256 + k] : W2r[(n - 64) * 256 + k]);
    } else if (i < 256 * 256 + 128 * 256 + 128 * 64) {
        int j = i - 256 * 256 - 128 * 256;
        g_B3h[j] = __float2half(Wd[j]);
    }
}

// write padded features (half) into right half of AXh. 16 lanes per row, 8 cols each.
__global__ void build_ax(const float* __restrict__ xm, const float* __restrict__ xp) {
    int t = blockIdx.x * blockDim.x + threadIdx.x;
    if (t >= NN * 16) return;
    int row = t >> 4, l = t & 15;
    int col = l * 8;
    float4 v0 = f4z(), v1 = f4z();
    if (row < NM) {
        if (col < 96) {
            v0 = *(const float4*)(xm + (size_t)row * 96 + col);
            v1 = *(const float4*)(xm + (size_t)row * 96 + col + 4);
        }
    } else {
        const float* xr = xp + (size_t)(row - NM) * 128 + col;
        v0 = *(const float4*)xr;
        v1 = *(const float4*)(xr + 4);
    }
    ((uint4*)g_AXh)[(size_t)row * 32 + 16 + l] = f8_to_h8(v0, v1);
}

// one thread per edge: both directions
__global__ void deg_count(const int* __restrict__ ei) {
    int e = blockIdx.x * blockDim.x + threadIdx.x;
    if (e >= E_EDGES) return;
    int p = __ldg(&ei[e]);
    int m = __ldg(&ei[E_EDGES + e]);
    atomicAdd(&g_deg[NM + m], 1);
    atomicAdd(&g_deg[p], 1);
}

__global__ void scanA(int n) {
    int i = blockIdx.x * 1024 + threadIdx.x;
    int v = (i < n) ? g_deg[i] : 0;
    int inc = warpScanInc(v);
    __shared__ int ws[32];
    int warp = threadIdx.x >> 5, lane = threadIdx.x & 31;
    if (lane == 31) ws[warp] = inc;
    __syncthreads();
    if (warp == 0) {
        int t = ws[lane];
        t = warpScanInc(t);
        ws[lane] = t;
    }
    __syncthreads();
    int base = (warp > 0) ? ws[warp - 1] : 0;
    if (i < n) g_rowptr[i] = base + inc - v;
    if (threadIdx.x == 1023) g_bsum[blockIdx.x] = base + inc;
}

__global__ void scanB(int nb) {
    int tid = threadIdx.x;  // 128 threads
    int v = (tid < nb) ? g_bsum[tid] : 0;
    int inc = warpScanInc(v);
    __shared__ int ws[4];
    if ((tid & 31) == 31) ws[tid >> 5] = inc;
    __syncthreads();
    int w = tid >> 5, base = 0;
    for (int i = 0; i < w; i++) base += ws[i];
    __syncthreads();
    if (tid < nb) g_bsum[tid] = base + inc - v;
}

__global__ void scanC(int n) {
    int i = blockIdx.x * 1024 + threadIdx.x;
    if (i < n) {
        int rp = g_rowptr[i] + g_bsum[blockIdx.x];
        g_rowptr[i] = rp;
        g_cursor[i] = rp;     // cursor starts at row start: fill_csr atomics give absolute pos
    }
}

// one thread per edge: both directions, cursor holds absolute position
__global__ void fill_csr(const int* __restrict__ ei) {
    int e = blockIdx.x * blockDim.x + threadIdx.x;
    if (e >= E_EDGES) return;
    int p = __ldg(&ei[e]);
    int m = __ldg(&ei[E_EDGES + e]);
    int pos1 = atomicAdd(&g_cursor[NM + m], 1);
    g_col[pos1] = p;
    int pos2 = atomicAdd(&g_cursor[p], 1);
    g_col[pos2] = NM + m;
}

// ---------------- aggregation ----------------
// Layer 1: 16 lanes per node; gather half feature rows (256B each), mean in fp32, write half.
__global__ void agg1_kernel() {
    int t = blockIdx.x * blockDim.x + threadIdx.x;
    int node = t >> 4;
    if (node >= NN) return;
    int l = t & 15;
    int start = g_rowptr[node];
    int d = g_deg[node];
    const uint4* AX4 = (const uint4*)g_AXh;
    float acc[8];
    #pragma unroll
    for (int i = 0; i < 8; i++) acc[i] = 0.f;
    int j = 0;
    for (; j + 4 <= d; j += 4) {
        int s0 = __ldg(&g_col[start + j]);
        int s1 = __ldg(&g_col[start + j + 1]);
        int s2 = __ldg(&g_col[start + j + 2]);
        int s3 = __ldg(&g_col[start + j + 3]);
        uint4 v0 = __ldg(&AX4[(size_t)s0 * 32 + 16 + l]);
        uint4 v1 = __ldg(&AX4[(size_t)s1 * 32 + 16 + l]);
        uint4 v2 = __ldg(&AX4[(size_t)s2 * 32 + 16 + l]);
        uint4 v3 = __ldg(&AX4[(size_t)s3 * 32 + 16 + l]);
        acc8(acc, v0); acc8(acc, v1); acc8(acc, v2); acc8(acc, v3);
    }
    for (; j < d; j++) {
        int s0 = __ldg(&g_col[start + j]);
        uint4 v0 = __ldg(&AX4[(size_t)s0 * 32 + 16 + l]);
        acc8(acc, v0);
    }
    float inv = 1.0f / fmaxf((float)d, 1.0f);
    uint4 o;
    o.x = h2u(__floats2half2_rn(acc[0] * inv, acc[1] * inv));
    o.y = h2u(__floats2half2_rn(acc[2] * inv, acc[3] * inv));
    o.z = h2u(__floats2half2_rn(acc[4] * inv, acc[5] * inv));
    o.w = h2u(__floats2half2_rn(acc[6] * inv, acc[7] * inv));
    ((uint4*)g_AXh)[(size_t)node * 32 + l] = o;
}

// Layer 2 fused: 8 lanes per node, 16B lane loads; z = mean(u_half) + v_f32 + b2 -> Zh half.
__global__ void agg2_kernel(const float* __restrict__ b2) {
    int t = blockIdx.x * blockDim.x + threadIdx.x;
    int node = t >> 3;
    if (node >= NN) return;
    int l = t & 7;
    int start = g_rowptr[node];
    int d = g_deg[node];
    const uint4* U4 = (const uint4*)g_Uh;   // 64 halves per row = 8 uint4
    float acc[8];
    #pragma unroll
    for (int i = 0; i < 8; i++) acc[i] = 0.f;
    int j = 0;
    for (; j + 4 <= d; j += 4) {
        int s0 = __ldg(&g_col[start + j]);
        int s1 = __ldg(&g_col[start + j + 1]);
        int s2 = __ldg(&g_col[start + j + 2]);
        int s3 = __ldg(&g_col[start + j + 3]);
        uint4 v0 = __ldg(&U4[(size_t)s0 * 8 + l]);
        uint4 v1 = __ldg(&U4[(size_t)s1 * 8 + l]);
        uint4 v2 = __ldg(&U4[(size_t)s2 * 8 + l]);
        uint4 v3 = __ldg(&U4[(size_t)s3 * 8 + l]);
        acc8(acc, v0); acc8(acc, v1); acc8(acc, v2); acc8(acc, v3);
    }
    for (; j < d; j++) {
        int s0 = __ldg(&g_col[start + j]);
        uint4 v0 = __ldg(&U4[(size_t)s0 * 8 + l]);
        acc8(acc, v0);
    }
    float inv = 1.0f / fmaxf((float)d, 1.0f);
    float4 vv0 = __ldg((const float4*)(g_Vf + (size_t)node * 64 + l * 8));
    float4 vv1 = __ldg((const float4*)(g_Vf + (size_t)node * 64 + l * 8 + 4));
    float4 bb0 = __ldg((const float4*)(b2 + l * 8));
    float4 bb1 = __ldg((const float4*)(b2 + l * 8 + 4));
    float z0 = acc[0] * inv + vv0.x + bb0.x;
    float z1 = acc[1] * inv + vv0.y + bb0.y;
    float z2 = acc[2] * inv + vv0.z + bb0.z;
    float z3 = acc[3] * inv + vv0.w + bb0.w;
    float z4 = acc[4] * inv + vv1.x + bb1.x;
    float z5 = acc[5] * inv + vv1.y + bb1.y;
    float z6 = acc[6] * inv + vv1.z + bb1.z;
    float z7 = acc[7] * inv + vv1.w + bb1.w;
    uint4 zh;
    zh.x = h2u(__floats2half2_rn(z0, z1));
    zh.y = h2u(__floats2half2_rn(z2, z3));
    zh.z = h2u(__floats2half2_rn(z4, z5));
    zh.w = h2u(__floats2half2_rn(z6, z7));
    ((uint4*)g_Zh)[(size_t)node * 8 + l] = zh;
}

// ---------------- fp16 mma.sync GEMM: C[M,N] = A[M,K] @ Bw[N,K]^T ----------------
// Tile 128x128, BK=64, 256 threads = 8 warps (4 m x 2 n), warp tile 32x64.
// EPI: 0 = none, 1 = bias+relu, 2 = bias, 3 = UV split (cols 0-63 half->g_Uh, 64-127 f32->g_Vf)
#define SROWH 72                 // halves per smem row (64 data + 8 pad)
#define TILEH (128 * SROWH)      // halves per tile buffer (18432 B)

template <int EPI, typename OutT>
__global__ void __launch_bounds__(256, 2) hgemm(
    const __half* __restrict__ A, const __half* __restrict__ Bw,
    const float* __restrict__ bias, OutT* __restrict__ C,
    int M, int N, int K)
{
    extern __shared__ __half smh[];
    __half* bufA[2] = { smh,             smh + 2 * TILEH };
    __half* bufB[2] = { smh + TILEH,     smh + 3 * TILEH };

    const int tid  = threadIdx.x;
    const int lane = tid & 31, warp = tid >> 5;
    const int warp_m = warp & 3, warp_n = warp >> 2;
    const int g = lane >> 2, tig = lane & 3;
    const int m0 = blockIdx.x * 128;
    const int n0 = blockIdx.y * 128;
    const int NC = K >> 6;          // K chunks of 64

    float acc[2][8][4];
    #pragma unroll
    for (int mt = 0; mt < 2; mt++)
        #pragma unroll
        for (int nt = 0; nt < 8; nt++)
            #pragma unroll
            for (int j = 0; j < 4; j++) acc[mt][nt][j] = 0.f;

    auto stage = [&](int c) {
        __half* As = bufA[c & 1];
        __half* Bs = bufB[c & 1];
        const int k0 = c * 64;
        #pragma unroll
        for (int i = 0; i < 4; i++) {
            int slot = tid + i * 256;            // 1024 slots = 128 rows x 8 segs
            int row = slot >> 3, seg = slot & 7; // seg = 8 halves (16B)
            __half* dA = As + row * SROWH + seg * 8;
            int gr = m0 + row;
            if (gr < M) {
                const __half* sA = A + (size_t)gr * K + k0 + seg * 8;
                uint32_t da = s2u(dA);
                asm volatile("cp.async.cg.shared.global [%0], [%1], 16;" :: "r"(da), "l"(sA));
            } else {
                *(uint4*)dA = make_uint4(0, 0, 0, 0);
            }
            __half* dB = Bs + row * SROWH + seg * 8;
            const __half* sB = Bw + (size_t)(n0 + row) * K + k0 + seg * 8;
            uint32_t db = s2u(dB);
            asm volatile("cp.async.cg.shared.global [%0], [%1], 16;" :: "r"(db), "l"(sB));
        }
        asm volatile("cp.async.commit_group;" ::: "memory");
    };

    stage(0);
    for (int c = 0; c < NC; c++) {
        if (c + 1 < NC) stage(c + 1);
        else asm volatile("cp.async.commit_group;" ::: "memory");
        asm volatile("cp.async.wait_group 1;" ::: "memory");
        __syncthreads();

        const __half* As = bufA[c & 1];
        const __half* Bs = bufB[c & 1];
        #pragma unroll
        for (int ks = 0; ks < 4; ks++) {
            const int kb = ks * 16 + 2 * tig;
            uint32_t afr[2][4];
            #pragma unroll
            for (int mt = 0; mt < 2; mt++) {
                const __half* base = As + (warp_m * 32 + mt * 16 + g) * SROWH + kb;
                afr[mt][0] = *(const uint32_t*)(base);
                afr[mt][1] = *(const uint32_t*)(base + 8 * SROWH);
                afr[mt][2] = *(const uint32_t*)(base + 8);
                afr[mt][3] = *(const uint32_t*)(base + 8 * SROWH + 8);
            }
            #pragma unroll
            for (int nt = 0; nt < 8; nt++) {
                const __half* bb = Bs + (warp_n * 64 + nt * 8 + g) * SROWH + kb;
                uint32_t b0 = *(const uint32_t*)(bb);
                uint32_t b1 = *(const uint32_t*)(bb + 8);
                mma16(acc[0][nt], afr[0], b0, b1);
                mma16(acc[1][nt], afr[1], b0, b1);
            }
        }
        __syncthreads();
    }

    // ---- epilogue ----
    #pragma unroll
    for (int mt = 0; mt < 2; mt++) {
        int r0 = m0 + warp_m * 32 + mt * 16 + g;
        #pragma unroll
        for (int nt = 0; nt < 8; nt++) {
            int col = n0 + warp_n * 64 + nt * 8 + 2 * tig;
            float2 v0 = make_float2(acc[mt][nt][0], acc[mt][nt][1]);
            float2 v1 = make_float2(acc[mt][nt][2], acc[mt][nt][3]);
            if (EPI == 1 || EPI == 2) {
                float2 bb = *(const float2*)(bias + col);
                v0.x += bb.x; v0.y += bb.y;
                v1.x += bb.x; v1.y += bb.y;
            }
            if (EPI == 1) {
                v0.x = fmaxf(v0.x, 0.f); v0.y = fmaxf(v0.y, 0.f);
                v1.x = fmaxf(v1.x, 0.f); v1.y = fmaxf(v1.y, 0.f);
            }
            if (EPI == 3) {
                // split: cols 0-63 -> g_Uh (half), cols 64-127 -> g_Vf (fp32)
                if (col < 64) {
                    uint32_t* U = (uint32_t*)g_Uh;
                    if (r0 < M)     U[((size_t)r0 * 64 + col) >> 1]       = h2u(__floats2half2_rn(v0.x, v0.y));
                    if (r0 + 8 < M) U[((size_t)(r0 + 8) * 64 + col) >> 1] = h2u(__floats2half2_rn(v1.x, v1.y));
                } else {
                    int c2 = col - 64;
                    if (r0 < M)     *(float2*)(g_Vf + (size_t)r0 * 64 + c2)       = v0;
                    if (r0 + 8 < M) *(float2*)(g_Vf + (size_t)(r0 + 8) * 64 + c2) = v1;
                }
            } else if (sizeof(OutT) == 2) {
                uint32_t* Ch = (uint32_t*)C;
                if (r0 < M)     Ch[((size_t)r0 * N + col) >> 1]       = h2u(__floats2half2_rn(v0.x, v0.y));
                if (r0 + 8 < M) Ch[((size_t)(r0 + 8) * N + col) >> 1] = h2u(__floats2half2_rn(v1.x, v1.y));
            } else {
                float* Cf = (float*)C;
                if (r0 < M)     *(float2*)(Cf + (size_t)r0 * N + col)       = v0;
                if (r0 + 8 < M) *(float2*)(Cf + (size_t)(r0 + 8) * N + col) = v1;
            }
        }
    }
}

// ---------------- edge logits: 8 lanes per edge, uint4 lane loads ----------------
__global__ void logits_kernel(const int* __restrict__ ei, float* __restrict__ out) {
    int t = blockIdx.x * blockDim.x + threadIdx.x;
    int e = t >> 3;
    if (e >= E_EDGES) return;
    int l = t & 7;
    int p = __ldg(&ei[e]);
    int m = __ldg(&ei[E_EDGES + e]);
    const uint4* Z4 = (const uint4*)g_Zh;
    uint4 a = __ldg(&Z4[(size_t)(NM + p) * 8 + l]);
    uint4 b = __ldg(&Z4[(size_t)m * 8 + l]);
    float2 a0 = __half22float2(u2h(a.x)), a1 = __half22float2(u2h(a.y));
    float2 a2 = __half22float2(u2h(a.z)), a3 = __half22float2(u2h(a.w));
    float2 b0 = __half22float2(u2h(b.x)), b1 = __half22float2(u2h(b.y));
    float2 b2 = __half22float2(u2h(b.z)), b3 = __half22float2(u2h(b.w));
    float s = a0.x * b0.x + a0.y * b0.y + a1.x * b1.x + a1.y * b1.y
            + a2.x * b2.x + a2.y * b2.y + a3.x * b3.x + a3.y * b3.y;
    s += __shfl_xor_sync(0xffffffffu, s, 4);
    s += __shfl_xor_sync(0xffffffffu, s, 2);
    s += __shfl_xor_sync(0xffffffffu, s, 1);
    if (l == 0) out[e] = s;
}

// ---------------- launch ----------------
extern "C" void kernel_launch(void* const* d_in, const int* in_sizes, int n_in,
                              void* d_out, int out_size) {
    const float* x_member   = (const float*)d_in[0];
    const float* x_provider = (const float*)d_in[1];
    const int*   edge_index = (const int*)d_in[2];
    const float* W1l = (const float*)d_in[3];
    const float* W1r = (const float*)d_in[4];
    const float* b1  = (const float*)d_in[5];
    const float* W2l = (const float*)d_in[6];
    const float* W2r = (const float*)d_in[7];
    const float* b2  = (const float*)d_in[8];
    const float* Wd  = (const float*)d_in[9];
    const float* bd  = (const float*)d_in[10];
    float* out = (float*)d_out;

    __half* g_AXh_p; cudaGetSymbolAddress((void**)&g_AXh_p, g_AXh);
    __half* g_Hh_p;  cudaGetSymbolAddress((void**)&g_Hh_p,  g_Hh);
    __half* g_Uh_p;  cudaGetSymbolAddress((void**)&g_Uh_p,  g_Uh);
    __half* g_Zh_p;  cudaGetSymbolAddress((void**)&g_Zh_p,  g_Zh);
    __half* g_B1_p;  cudaGetSymbolAddress((void**)&g_B1_p,  g_B1h);
    __half* g_B2_p;  cudaGetSymbolAddress((void**)&g_B2_p,  g_B2h);
    __half* g_B3_p;  cudaGetSymbolAddress((void**)&g_B3_p,  g_B3h);

    const int SMEM = 4 * TILEH * (int)sizeof(__half);  // 73728
    cudaFuncSetAttribute((const void*)hgemm<1, __half>,
                         cudaFuncAttributeMaxDynamicSharedMemorySize, SMEM);
    cudaFuncSetAttribute((const void*)hgemm<3, __half>,
                         cudaFuncAttributeMaxDynamicSharedMemorySize, SMEM);
    cudaFuncSetAttribute((const void*)hgemm<2, float>,
                         cudaFuncAttributeMaxDynamicSharedMemorySize, SMEM);

    const int NB = (NN + 1023) / 1024;  // 98
    const int GT = (NN + 127) / 128;    // 782

    zero_counters<<<(NN + 255) / 256, 256>>>();
    pack_weights<<<(256 * 256 + 128 * 256 + 128 * 64 + 255) / 256, 256>>>(W1l, W1r, W2l, W2r, Wd);
    build_ax<<<(NN * 16 + 255) / 256, 256>>>(x_member, x_provider);
    deg_count<<<(E_EDGES + 255) / 256, 256>>>(edge_index);
    scanA<<<NB, 1024>>>(NN);
    scanB<<<1, 128>>>(NB);
    scanC<<<NB, 1024>>>(NN);
    fill_csr<<<(E_EDGES + 255) / 256, 256>>>(edge_index);

    // layer 1: AXh = [agg | x] (half), H = relu(AXh @ B1^T + b1) -> half
    agg1_kernel<<<(NN * 16 + 255) / 256, 256>>>();
    hgemm<1, __half><<<dim3(GT, 2), 256, SMEM>>>(g_AXh_p, g_B1_p, b1, g_Hh_p, NN, 256, 256);

    // layer 2 pre-projection: [u|v] = H @ [W2l|W2r]^T, u->half g_Uh, v->fp32 g_Vf
    hgemm<3, __half><<<dim3(GT, 1), 256, SMEM>>>(g_Hh_p, g_B2_p, nullptr, g_Uh_p, NN, 128, 256);

    // layer 2 aggregation + z (writes Zh half)
    agg2_kernel<<<(NN * 8 + 255) / 256, 256>>>(b2);

    // decoder straight into d_out
    hgemm<2, float><<<dim3(GT, 1), 256, SMEM>>>(g_Zh_p, g_B3_p, bd, out, NN, 128, 64);

    // edge logits
    logits_kernel<<<(E_EDGES * 8 + 255) / 256, 256>>>(edge_index, out + (size_t)2 * NM * 128);

    (void)in_sizes; (void)n_in; (void)out_size;
}